// round 4
// baseline (speedup 1.0000x reference)
#include <cuda_runtime.h>
#include <math.h>

#define NN    20000
#define NEDGE 320000

// ---------------- device scratch (static, no allocs) ----------------
__device__ __align__(16) float g_s_up[NN * 64];
__device__ __align__(16) float g_v_up[NN * 192];
__device__ __align__(16) float g_msg_s[NN * 128];
__device__ __align__(16) float g_msg_v[NN * 576];           // packed [n][row*3+m]
__device__ __align__(16) float g_tpw[(size_t)NEDGE * 320];  // edge MLP output
__device__ __align__(16) float g_wfrag[29184];              // fp32 fragment weights (prescaled)

__device__ __forceinline__ void red4(float* p, float a, float b, float c, float d) {
    asm volatile("red.global.add.v4.f32 [%0], {%1,%2,%3,%4};"
                 :: "l"(p), "f"(a), "f"(b), "f"(c), "f"(d) : "memory");
}
__device__ __forceinline__ float silu_n(float y, float cs) {
    return cs * y * (1.f / (1.f + __expf(-y)));
}
__device__ __forceinline__ unsigned f2tf(float x) {
    unsigned r; asm("cvt.rna.tf32.f32 %0, %1;" : "=r"(r) : "f"(x)); return r;
}
__device__ __forceinline__ void split2(float x, unsigned& h, unsigned& l) {
    h = f2tf(x);
    l = f2tf(x - __uint_as_float(h));
}
__device__ __forceinline__ void mma8(float* c, const unsigned* a, unsigned b0, unsigned b1) {
    asm volatile("mma.sync.aligned.m16n8k8.row.col.f32.tf32.tf32.f32 "
                 "{%0,%1,%2,%3}, {%4,%5,%6,%7}, {%8,%9}, {%0,%1,%2,%3};"
                 : "+f"(c[0]), "+f"(c[1]), "+f"(c[2]), "+f"(c[3])
                 : "r"(a[0]), "r"(a[1]), "r"(a[2]), "r"(a[3]), "r"(b0), "r"(b1));
}
// 3-pass tf32 accumulate: C += A*B with ~fp32 accuracy
__device__ __forceinline__ void mma3(float* c, const unsigned* ah, const unsigned* al,
                                     float b0, float b1) {
    unsigned b0h, b0l, b1h, b1l;
    split2(b0, b0h, b0l);
    split2(b1, b1h, b1l);
    mma8(c, ah, b0h, b1h);
    mma8(c, ah, b0l, b1l);
    mma8(c, al, b0h, b1h);
}

// ---------------- kernel A: node up-projection ----------------
__global__ void node_up_kernel(const float* __restrict__ nf,
                               const float* __restrict__ Wup0,
                               const float* __restrict__ Wup1) {
    __shared__ float sW0[4096];
    __shared__ float sW1[4096];
    __shared__ float sIn[256];
    int t = threadIdx.x;
    for (int i = t; i < 4096; i += 256) {
        sW0[i] = Wup0[i] * 0.125f;
        sW1[i] = Wup1[i] * 0.125f;
    }
    __syncthreads();
    int base = blockIdx.x * 8;
    for (int nn = 0; nn < 8; nn++) {
        int n = base + nn;
        sIn[t] = nf[n * 256 + t];
        __syncthreads();
        if (t < 64) {
            float acc = 0.f;
#pragma unroll 16
            for (int c = 0; c < 64; c++) acc = fmaf(sIn[c], sW0[c * 64 + t], acc);
            g_s_up[n * 64 + t] = acc;
        } else {
            int k = (t - 64) / 3, m = (t - 64) - 3 * k;
            float acc = 0.f;
#pragma unroll 16
            for (int c = 0; c < 64; c++) acc = fmaf(sIn[64 + c * 3 + m], sW1[c * 64 + k], acc);
            g_v_up[n * 192 + k * 3 + m] = acc;
        }
        __syncthreads();
    }
}

// ---------------- zero message accumulators ----------------
__global__ void zero_msg_kernel() {
    int idx = blockIdx.x * blockDim.x + threadIdx.x;
    int stride = gridDim.x * blockDim.x;
    float4 z = make_float4(0.f, 0.f, 0.f, 0.f);
    for (int k = idx; k < NN * 128 / 4; k += stride) ((float4*)g_msg_s)[k] = z;
    for (int k = idx; k < NN * 576 / 4; k += stride) ((float4*)g_msg_v)[k] = z;
}

// ---------------- weight fragment prep (fp32, prescaled) ----------------
// layout: W1f @0 (1x8 tiles), W2f @512 (8x8), W3f @4608 (8x8), W4f @8704 (8x40)
// per (kt,nt): 32 lanes x 2 floats: b0=W[kt*8+tg][nt*8+g], b1=W[kt*8+tg+4][nt*8+g]
__global__ void wprep_kernel(const float* __restrict__ W1, const float* __restrict__ W2,
                             const float* __restrict__ W3, const float* __restrict__ W4) {
    int p = blockIdx.x * blockDim.x + threadIdx.x;
    if (p >= 14592) return;
    const float* W; int NT, Ncols, base, off; float scale;
    if (p < 256)       { W = W1; NT = 8;  Ncols = 64;  base = 0;    off = p;        scale = 0.3535533905932738f; }
    else if (p < 2304) { W = W2; NT = 8;  Ncols = 64;  base = 512;  off = p - 256;  scale = 0.125f; }
    else if (p < 4352) { W = W3; NT = 8;  Ncols = 64;  base = 4608; off = p - 2304; scale = 0.125f; }
    else               { W = W4; NT = 40; Ncols = 320; base = 8704; off = p - 4352; scale = 0.125f; }
    int lane = off & 31, ktnt = off >> 5;
    int nt = ktnt % NT, kt = ktnt / NT;
    int g = lane >> 2, tg = lane & 3;
    g_wfrag[base + off * 2]     = W[(kt * 8 + tg) * Ncols + nt * 8 + g] * scale;
    g_wfrag[base + off * 2 + 1] = W[(kt * 8 + tg + 4) * Ncols + nt * 8 + g] * scale;
}

// ---------------- edge MLP: tf32x3, shfl relayout, 16 edges/warp ----------------
// C frag of tile nt: lane(g,tg) holds rows (g, g+8), cols (nt*8+2tg, +1).
// A frag of tile kt needs rows (g, g+8), cols (kt*8+tg, kt*8+tg+4):
// same rows -> intra-quad shfl column exchange only.
__device__ __forceinline__ void extract_frags(const float H[8][4],
                                              unsigned Ah[8][4], unsigned Al[8][4],
                                              int lane, int tg) {
    int s0 = (lane & 28) | (tg >> 1);
    int s1 = s0 + 2;
    bool odd = (tg & 1);
#pragma unroll
    for (int kt = 0; kt < 8; kt++) {
        float v00 = __shfl_sync(0xffffffffu, H[kt][0], s0);
        float v01 = __shfl_sync(0xffffffffu, H[kt][1], s0);
        float v20 = __shfl_sync(0xffffffffu, H[kt][2], s0);
        float v21 = __shfl_sync(0xffffffffu, H[kt][3], s0);
        float w00 = __shfl_sync(0xffffffffu, H[kt][0], s1);
        float w01 = __shfl_sync(0xffffffffu, H[kt][1], s1);
        float w20 = __shfl_sync(0xffffffffu, H[kt][2], s1);
        float w21 = __shfl_sync(0xffffffffu, H[kt][3], s1);
        split2(odd ? v01 : v00, Ah[kt][0], Al[kt][0]);
        split2(odd ? v21 : v20, Ah[kt][1], Al[kt][1]);
        split2(odd ? w01 : w00, Ah[kt][2], Al[kt][2]);
        split2(odd ? w21 : w20, Ah[kt][3], Al[kt][3]);
    }
}

__global__ void __launch_bounds__(512, 1) mlp_kernel(const float* __restrict__ ef, float cs) {
    extern __shared__ float wf[];    // 29184 floats
    int t = threadIdx.x;
    for (int i = t; i < 29184; i += 512) wf[i] = g_wfrag[i];
    __syncthreads();
    int warp = t >> 5, lane = t & 31, g = lane >> 2, tg = lane & 3;
    int base = (blockIdx.x * 16 + warp) * 16;

    float H[8][4];
    // ---- layer 1 (8 -> 64) ----
    {
        unsigned Ah[4], Al[4];
        split2(ef[(base + g) * 8 + tg],         Ah[0], Al[0]);
        split2(ef[(base + g + 8) * 8 + tg],     Ah[1], Al[1]);
        split2(ef[(base + g) * 8 + tg + 4],     Ah[2], Al[2]);
        split2(ef[(base + g + 8) * 8 + tg + 4], Ah[3], Al[3]);
#pragma unroll
        for (int nt = 0; nt < 8; nt++) {
            float C[4] = {0.f, 0.f, 0.f, 0.f};
            float2 b = ((const float2*)wf)[nt * 32 + lane];
            mma3(C, Ah, Al, b.x, b.y);
#pragma unroll
            for (int i = 0; i < 4; i++) H[nt][i] = silu_n(C[i], cs);
        }
    }
    // ---- layers 2, 3 (64 -> 64) ----
#pragma unroll 1
    for (int l = 0; l < 2; l++) {
        const float2* wl = (const float2*)(wf + (l == 0 ? 512 : 4608));
        unsigned Ah[8][4], Al[8][4];
        extract_frags(H, Ah, Al, lane, tg);
        float C[8][4];
#pragma unroll
        for (int nt = 0; nt < 8; nt++)
            C[nt][0] = C[nt][1] = C[nt][2] = C[nt][3] = 0.f;
#pragma unroll
        for (int kt = 0; kt < 8; kt++) {
#pragma unroll
            for (int nt = 0; nt < 8; nt++) {
                float2 b = wl[(kt * 8 + nt) * 32 + lane];
                mma3(C[nt], Ah[kt], Al[kt], b.x, b.y);
            }
        }
#pragma unroll
        for (int nt = 0; nt < 8; nt++)
#pragma unroll
            for (int i = 0; i < 4; i++) H[nt][i] = silu_n(C[nt][i], cs);
    }
    // ---- layer 4 (64 -> 320) ----
    {
        unsigned Ah[8][4], Al[8][4];
        extract_frags(H, Ah, Al, lane, tg);
        const float2* wl = (const float2*)(wf + 8704);
#pragma unroll 1
        for (int chunk = 0; chunk < 5; chunk++) {
            float C[8][4];
#pragma unroll
            for (int nt = 0; nt < 8; nt++)
                C[nt][0] = C[nt][1] = C[nt][2] = C[nt][3] = 0.f;
#pragma unroll
            for (int kt = 0; kt < 8; kt++) {
#pragma unroll
                for (int nt = 0; nt < 8; nt++) {
                    float2 b = wl[(kt * 40 + chunk * 8 + nt) * 32 + lane];
                    mma3(C[nt], Ah[kt], Al[kt], b.x, b.y);
                }
            }
#pragma unroll
            for (int nt = 0; nt < 8; nt++) {
                int col = (chunk * 8 + nt) * 8 + 2 * tg;
                *(float2*)&g_tpw[(size_t)(base + g) * 320 + col]     = make_float2(C[nt][0], C[nt][1]);
                *(float2*)&g_tpw[(size_t)(base + g + 8) * 320 + col] = make_float2(C[nt][2], C[nt][3]);
            }
        }
    }
}

// ---------------- messages + scatter (packed vector layout) ----------------
__device__ __forceinline__ void do_messages(int e, int lane, const float* __restrict__ tw,
                                            const float* __restrict__ ea,
                                            const int* __restrict__ ie,
                                            const int* __restrict__ je) {
    const float INV_SQRT3 = 0.5773502691896258f;
    const float INV_SQRT2 = 0.7071067811865476f;
    int inode = __ldg(&ie[e]);
    int jnode = __ldg(&je[e]);
    float4 e4 = *(const float4*)&ea[e * 4];
    float eas = e4.x, v0e = e4.y, v1e = e4.z, v2e = e4.w;
    const float* su = g_s_up + inode * 64;
    const float* vu = g_v_up + inode * 192;
    float* ms = g_msg_s + jnode * 128;
    float* mv = g_msg_v + jnode * 576;

    // scalar messages: m0 (lanes 0-15), m1 (lanes 16-31)
    if (lane < 16) {
        int c = 4 * lane;
        float4 xs = *(const float4*)(su + c);
        red4(ms + c, tw[c] * xs.x * eas, tw[c + 1] * xs.y * eas,
                     tw[c + 2] * xs.z * eas, tw[c + 3] * xs.w * eas);
    } else {
        int k = lane - 16;
        int c = 4 * k;
        const float* vp = vu + c * 3;
        float4 p0 = *(const float4*)(vp);
        float4 p1 = *(const float4*)(vp + 4);
        float4 p2 = *(const float4*)(vp + 8);
        float d0 = p0.x * v0e + p0.y * v1e + p0.z * v2e;
        float d1 = p0.w * v0e + p1.x * v1e + p1.y * v2e;
        float d2 = p1.z * v0e + p1.w * v1e + p2.x * v2e;
        float d3 = p2.y * v0e + p2.z * v1e + p2.w * v2e;
        red4(ms + 64 + c, tw[64 + c] * d0 * INV_SQRT3, tw[64 + c + 1] * d1 * INV_SQRT3,
                          tw[64 + c + 2] * d2 * INV_SQRT3, tw[64 + c + 3] * d3 * INV_SQRT3);
    }
    // vector messages: lanes 0-23, 8 rows each -> 24 floats -> 6 red4
    if (lane < 24) {
        int grp = lane >> 3;            // 0:m2, 1:m3, 2:m4
        int cl = (lane & 7) * 8;
        float vals[24];
#pragma unroll
        for (int rr = 0; rr < 8; rr++) {
            int c = cl + rr;
            float o0, o1, o2;
            if (grp == 0) {
                float tmp = tw[128 + c] * su[c];
                o0 = tmp * v0e; o1 = tmp * v1e; o2 = tmp * v2e;
            } else if (grp == 1) {
                float w = tw[192 + c] * eas;
                o0 = w * vu[3 * c]; o1 = w * vu[3 * c + 1]; o2 = w * vu[3 * c + 2];
            } else {
                float w = tw[256 + c] * INV_SQRT2;
                float x0 = vu[3 * c], x1 = vu[3 * c + 1], x2 = vu[3 * c + 2];
                o0 = w * (x1 * v2e - x2 * v1e);
                o1 = w * (x2 * v0e - x0 * v2e);
                o2 = w * (x0 * v1e - x1 * v0e);
            }
            vals[rr * 3 + 0] = o0; vals[rr * 3 + 1] = o1; vals[rr * 3 + 2] = o2;
        }
        float* dst = mv + lane * 24;
#pragma unroll
        for (int i = 0; i < 6; i++)
            red4(dst + 4 * i, vals[4 * i], vals[4 * i + 1], vals[4 * i + 2], vals[4 * i + 3]);
    }
}

__global__ void __launch_bounds__(256, 1) msg_kernel(const float* __restrict__ ea,
                                                     const int* __restrict__ ie,
                                                     const int* __restrict__ je) {
    int gw = (blockIdx.x * 256 + threadIdx.x) >> 5;
    int lane = threadIdx.x & 31;
    int e0 = gw * 32;
#pragma unroll 1
    for (int k = 0; k < 32; k++)
        do_messages(e0 + k, lane, g_tpw + (size_t)(e0 + k) * 320, ea, ie, je);
}

// ---------------- finalize: 2-node register blocking ----------------
__global__ void __launch_bounds__(512, 1) finalize_kernel(
    const float* __restrict__ Wl0, const float* __restrict__ Wl1,
    const float* __restrict__ Ws0c1, const float* __restrict__ Ws0c2,
    const float* __restrict__ Ws0c3, const float* __restrict__ Ws1c1,
    const float* __restrict__ Ws1c2, const float* __restrict__ Ws1c3,
    const float* __restrict__ Wp0, const float* __restrict__ Wp1,
    const int* __restrict__ zn, float* __restrict__ out) {
    const float INV_SQRT3 = 0.5773502691896258f;
    const float INV_SQRT_2C = 0.08838834764831845f;
    const float INV_SQRT_3C = 0.07216878364870323f;
    extern __shared__ float sh[];
    float* sL0 = sh;              // 8192
    float* sL1 = sh + 8192;       // 12288
    float* sP0 = sh + 20480;      // 4096
    float* sP1 = sh + 24576;      // 4096
    float* sT01 = sh + 28672;     // 640
    float* sT02 = sh + 29312;     // 1280
    float* sT03 = sh + 30592;     // 1280
    float* sT11 = sh + 31872;     // 640
    float* sT12 = sh + 32512;     // 640
    float* sT13 = sh + 33152;     // 1280
    float* sDyn = sh + 34432;     // 2 subgroups x 2432

    int t = threadIdx.x;
    for (int i = t; i < 8192; i += 512)  sL0[i] = Wl0[i] * INV_SQRT_2C;
    for (int i = t; i < 12288; i += 512) sL1[i] = Wl1[i] * INV_SQRT_3C;
    for (int i = t; i < 4096; i += 512) { sP0[i] = Wp0[i] * 0.125f; sP1[i] = Wp1[i] * 0.125f; }
    for (int i = t; i < 640; i += 512) { sT01[i] = Ws0c1[i]; sT11[i] = Ws1c1[i]; sT12[i] = Ws1c2[i]; }
    for (int i = t; i < 1280; i += 512) { sT02[i] = Ws0c2[i]; sT03[i] = Ws0c3[i]; sT13[i] = Ws1c3[i]; }
    __syncthreads();

    int sub = t >> 8;
    int tt = t & 255;
    float* st  = sDyn + sub * 2432;
    float* ms  = st;           // [2][128]
    float* mv  = st + 256;     // [2][576]
    float* v2s = st + 1408;    // [2][192]
    float* oss = st + 1792;    // [2][64]
    float* cfs = st + 1920;    // [2][64]
    float* ovs = st + 2048;    // [2][192]

    for (int p = blockIdx.x; p < NN / 4; p += gridDim.x) {
        int n0 = 4 * p + 2 * sub;
        ms[tt] = g_msg_s[(n0 + (tt >> 7)) * 128 + (tt & 127)];
#pragma unroll
        for (int i = 0; i < 5; i++) {
            int idx = i * 256 + tt;
            if (idx < 1152) {
                int nd = idx >= 576;
                mv[idx] = g_msg_v[(n0 + nd) * 576 + (idx - nd * 576)];
            }
        }
        __syncthreads();

        float s2a = 0.f, s2b = 0.f;
        if (tt < 64) {
            int col = tt;
#pragma unroll 8
            for (int c = 0; c < 128; c++) {
                float w = sL0[c * 64 + col];
                s2a = fmaf(ms[c], w, s2a);
                s2b = fmaf(ms[128 + c], w, s2b);
            }
        } else {
            int k = (tt - 64) / 3, m = (tt - 64) - 3 * k;
            float a0 = 0.f, a1 = 0.f;
#pragma unroll 8
            for (int r = 0; r < 192; r++) {
                float w = sL1[r * 64 + k];
                a0 = fmaf(mv[r * 3 + m], w, a0);
                a1 = fmaf(mv[576 + r * 3 + m], w, a1);
            }
            v2s[k * 3 + m] = a0;
            v2s[192 + k * 3 + m] = a1;
        }
        __syncthreads();

        if (tt < 64) {
            int k = tt;
#pragma unroll
            for (int n = 0; n < 2; n++) {
                float s2 = n ? s2b : s2a;
                int z = zn[n0 + n];
                float a = v2s[n * 192 + 3 * k], b = v2s[n * 192 + 3 * k + 1], c = v2s[n * 192 + 3 * k + 2];
                float vv = (a * a + b * b + c * c) * INV_SQRT3;
                float s22 = s2 * s2;
                float outs = sT01[z * 64 + k] * s2 + sT02[(2 * z) * 64 + k] * s22
                           + sT02[(2 * z + 1) * 64 + k] * vv
                           + sT03[(2 * z) * 64 + k] * s22 * s2
                           + sT03[(2 * z + 1) * 64 + k] * s2 * vv;
                float coef = sT11[z * 64 + k] + sT12[z * 64 + k] * s2
                           + sT13[(2 * z) * 64 + k] * s22 + sT13[(2 * z + 1) * 64 + k] * vv;
                oss[n * 64 + k] = outs;
                cfs[n * 64 + k] = coef;
            }
        }
        __syncthreads();
        if (tt >= 64) {
            int idx = tt - 64;
            int k = idx / 3;
            ovs[idx]       = cfs[k] * v2s[idx];
            ovs[192 + idx] = cfs[64 + k] * v2s[192 + idx];
        }
        __syncthreads();

        if (tt < 64) {
            float a0 = 0.f, a1 = 0.f;
#pragma unroll 8
            for (int c = 0; c < 64; c++) {
                float w = sP0[c * 64 + tt];
                a0 = fmaf(oss[c], w, a0);
                a1 = fmaf(oss[64 + c], w, a1);
            }
            out[n0 * 256 + tt] = a0;
            out[(n0 + 1) * 256 + tt] = a1;
        } else {
            int idx = tt - 64;
            int k = idx / 3, m = idx - 3 * k;
            float a0 = 0.f, a1 = 0.f;
#pragma unroll 8
            for (int c = 0; c < 64; c++) {
                float w = sP1[c * 64 + k];
                a0 = fmaf(ovs[c * 3 + m], w, a0);
                a1 = fmaf(ovs[192 + c * 3 + m], w, a1);
            }
            out[n0 * 256 + 64 + idx] = a0;
            out[(n0 + 1) * 256 + 64 + idx] = a1;
        }
        __syncthreads();
    }
}

// ---------------- host launcher ----------------
extern "C" void kernel_launch(void* const* d_in, const int* in_sizes, int n_in,
                              void* d_out, int out_size) {
    const float* nf   = (const float*)d_in[0];
    const float* ef   = (const float*)d_in[1];
    const float* ea   = (const float*)d_in[2];
    const int*   ie   = (const int*)d_in[3];
    const int*   je   = (const int*)d_in[4];
    const int*   zn   = (const int*)d_in[5];
    const float* Wup0 = (const float*)d_in[6];
    const float* Wup1 = (const float*)d_in[7];
    const float* Wm1  = (const float*)d_in[8];
    const float* Wm2  = (const float*)d_in[9];
    const float* Wm3  = (const float*)d_in[10];
    const float* Wm4  = (const float*)d_in[11];
    const float* Wl0  = (const float*)d_in[12];
    const float* Wl1  = (const float*)d_in[13];
    const float* Ws0c1 = (const float*)d_in[14];
    const float* Ws0c2 = (const float*)d_in[15];
    const float* Ws0c3 = (const float*)d_in[16];
    const float* Ws1c1 = (const float*)d_in[17];
    const float* Ws1c2 = (const float*)d_in[18];
    const float* Ws1c3 = (const float*)d_in[19];
    const float* Wp0  = (const float*)d_in[20];
    const float* Wp1  = (const float*)d_in[21];
    float* out = (float*)d_out;

    // C_SILU via trapezoid on R (matches Gauss-Hermite to <1e-7)
    double m2 = 0.0;
    const double hstep = 1.0 / 128.0;
    for (int i = -14 * 128; i <= 14 * 128; i++) {
        double z = i * hstep;
        double f = z / (1.0 + exp(-z));
        m2 += exp(-0.5 * z * z) * f * f;
    }
    m2 *= hstep / sqrt(2.0 * 3.141592653589793);
    float cs = (float)(1.0 / sqrt(m2));

    cudaFuncSetAttribute(mlp_kernel, cudaFuncAttributeMaxDynamicSharedMemorySize, 116736);
    cudaFuncSetAttribute(finalize_kernel, cudaFuncAttributeMaxDynamicSharedMemorySize, 157184);

    node_up_kernel<<<2500, 256>>>(nf, Wup0, Wup1);
    zero_msg_kernel<<<2048, 256>>>();
    wprep_kernel<<<57, 256>>>(Wm1, Wm2, Wm3, Wm4);
    mlp_kernel<<<1250, 512, 116736>>>(ef, cs);
    msg_kernel<<<1250, 256>>>(ea, ie, je);
    finalize_kernel<<<296, 512, 157184>>>(Wl0, Wl1, Ws0c1, Ws0c2, Ws0c3,
                                          Ws1c1, Ws1c2, Ws1c3, Wp0, Wp1, zn, out);
}

// round 5
// speedup vs baseline: 1.5913x; 1.5913x over previous
#include <cuda_runtime.h>
#include <math.h>

#define NN    20000
#define NEDGE 320000

// ---------------- device scratch (static, no allocs) ----------------
__device__ __align__(16) float g_s_up[NN * 64];
__device__ __align__(16) float g_v_up[NN * 192];
__device__ __align__(16) float g_msg_s[NN * 128];
__device__ __align__(16) float g_msg_v[NN * 576];           // packed [n][row*3+m]
__device__ __align__(16) float g_tpw[(size_t)NEDGE * 320];  // edge MLP output
__device__ uint4 g_wfragB[7424];                            // bf16 hi/lo weight frags
__device__ int g_deg[NN];
__device__ int g_cursor[NN];
__device__ int g_off[NN + 1];
__device__ int g_sorted[NEDGE];

__device__ __forceinline__ float silu_n(float y, float cs) {
    return cs * y * (1.f / (1.f + __expf(-y)));
}
// pack (x0,x1) into bf16x2 hi part h (x0 in low half) and residual lo part l
__device__ __forceinline__ void bsplit2(float x0, float x1, unsigned& h, unsigned& l) {
    asm("cvt.rn.bf16x2.f32 %0, %1, %2;" : "=r"(h) : "f"(x1), "f"(x0));
    float f0 = __uint_as_float(h << 16);
    float f1 = __uint_as_float(h & 0xffff0000u);
    asm("cvt.rn.bf16x2.f32 %0, %1, %2;" : "=r"(l) : "f"(x1 - f1), "f"(x0 - f0));
}
__device__ __forceinline__ void mma16(float* c, const unsigned* a, unsigned b0, unsigned b1) {
    asm volatile("mma.sync.aligned.m16n8k16.row.col.f32.bf16.bf16.f32 "
                 "{%0,%1,%2,%3}, {%4,%5,%6,%7}, {%8,%9}, {%0,%1,%2,%3};"
                 : "+f"(c[0]), "+f"(c[1]), "+f"(c[2]), "+f"(c[3])
                 : "r"(a[0]), "r"(a[1]), "r"(a[2]), "r"(a[3]), "r"(b0), "r"(b1));
}
__device__ __forceinline__ void mma3b(float* c, const unsigned* ah, const unsigned* al, uint4 b) {
    mma16(c, ah, b.x, b.y);   // Ah * Bh
    mma16(c, ah, b.z, b.w);   // Ah * Bl
    mma16(c, al, b.x, b.y);   // Al * Bh
}

// ---------------- kernel A: node up-projection ----------------
__global__ void node_up_kernel(const float* __restrict__ nf,
                               const float* __restrict__ Wup0,
                               const float* __restrict__ Wup1) {
    __shared__ float sW0[4096];
    __shared__ float sW1[4096];
    __shared__ float sIn[256];
    int t = threadIdx.x;
    for (int i = t; i < 4096; i += 256) {
        sW0[i] = Wup0[i] * 0.125f;
        sW1[i] = Wup1[i] * 0.125f;
    }
    __syncthreads();
    int base = blockIdx.x * 8;
    for (int nn = 0; nn < 8; nn++) {
        int n = base + nn;
        sIn[t] = nf[n * 256 + t];
        __syncthreads();
        if (t < 64) {
            float acc = 0.f;
#pragma unroll 16
            for (int c = 0; c < 64; c++) acc = fmaf(sIn[c], sW0[c * 64 + t], acc);
            g_s_up[n * 64 + t] = acc;
        } else {
            int k = (t - 64) / 3, m = (t - 64) - 3 * k;
            float acc = 0.f;
#pragma unroll 16
            for (int c = 0; c < 64; c++) acc = fmaf(sIn[64 + c * 3 + m], sW1[c * 64 + k], acc);
            g_v_up[n * 192 + k * 3 + m] = acc;
        }
        __syncthreads();
    }
}

// ---------------- destination-sort infrastructure ----------------
__global__ void zero_idx_kernel() {
    int i = blockIdx.x * 256 + threadIdx.x;
    if (i < NN) { g_deg[i] = 0; g_cursor[i] = 0; }
}
__global__ void hist_kernel(const int* __restrict__ je) {
    int i = blockIdx.x * 256 + threadIdx.x;
    if (i < NEDGE) atomicAdd(&g_deg[je[i]], 1);
}
__global__ void scan_kernel() {
    __shared__ int partial[1024];
    int t = threadIdx.x;
    int base = t * 20;
    int cnt[20];
    int sum = 0;
#pragma unroll
    for (int i = 0; i < 20; i++) {
        int v = (base + i < NN) ? g_deg[base + i] : 0;
        cnt[i] = v; sum += v;
    }
    partial[t] = sum;
    __syncthreads();
    for (int s = 1; s < 1024; s <<= 1) {
        int v = (t >= s) ? partial[t - s] : 0;
        __syncthreads();
        partial[t] += v;
        __syncthreads();
    }
    int run = (t == 0) ? 0 : partial[t - 1];
#pragma unroll
    for (int i = 0; i < 20; i++) {
        if (base + i < NN) g_off[base + i] = run;
        run += cnt[i];
    }
    if (t == 1023) g_off[NN] = run;
}
__global__ void scatter_kernel(const int* __restrict__ je) {
    int i = blockIdx.x * 256 + threadIdx.x;
    if (i < NEDGE) {
        int j = je[i];
        int p = atomicAdd(&g_cursor[j], 1);
        g_sorted[g_off[j] + p] = i;
    }
}

// ---------------- weight fragment prep: bf16 hi/lo, prescaled ----------------
// tiles: [0,8) L1 nt=t | [8,40) L2 | [40,72) L3 | [72,232) L4 kt*40+chunk*8+nt
__global__ void wprep_kernel(const float* __restrict__ W1, const float* __restrict__ W2,
                             const float* __restrict__ W3, const float* __restrict__ W4) {
    int p = blockIdx.x * blockDim.x + threadIdx.x;
    if (p >= 7424) return;
    int tile = p >> 5, lane = p & 31;
    int g = lane >> 2, tg = lane & 3;
    const float* W; int Ncols, Krows, kt, nglob; float scale;
    if (tile < 8)       { W = W1; Ncols = 64;  Krows = 8;  kt = 0; nglob = tile * 8 + g; scale = 0.3535533905932738f; }
    else if (tile < 40) { W = W2; Ncols = 64;  Krows = 64; int off = tile - 8;  kt = off >> 3; nglob = (off & 7) * 8 + g; scale = 0.125f; }
    else if (tile < 72) { W = W3; Ncols = 64;  Krows = 64; int off = tile - 40; kt = off >> 3; nglob = (off & 7) * 8 + g; scale = 0.125f; }
    else                { W = W4; Ncols = 320; Krows = 64; int off = tile - 72; kt = off / 40; nglob = (off % 40) * 8 + g; scale = 0.125f; }
    int k0 = kt * 16 + 2 * tg;
    float w0 = (k0     < Krows) ? W[(k0)     * Ncols + nglob] * scale : 0.f;
    float w1 = (k0 + 1 < Krows) ? W[(k0 + 1) * Ncols + nglob] * scale : 0.f;
    float w2 = (k0 + 8 < Krows) ? W[(k0 + 8) * Ncols + nglob] * scale : 0.f;
    float w3 = (k0 + 9 < Krows) ? W[(k0 + 9) * Ncols + nglob] * scale : 0.f;
    unsigned h0, l0, h1, l1;
    bsplit2(w0, w1, h0, l0);
    bsplit2(w2, w3, h1, l1);
    g_wfragB[p] = make_uint4(h0, h1, l0, l1);
}

// ---------------- edge MLP: bf16x3 m16n8k16, zero-shuffle relayout ----------------
__device__ __forceinline__ void extract_bf(const float H[8][4], unsigned Ah[4][4], unsigned Al[4][4]) {
#pragma unroll
    for (int kt = 0; kt < 4; kt++) {
        bsplit2(H[2 * kt][0],     H[2 * kt][1],     Ah[kt][0], Al[kt][0]);
        bsplit2(H[2 * kt][2],     H[2 * kt][3],     Ah[kt][1], Al[kt][1]);
        bsplit2(H[2 * kt + 1][0], H[2 * kt + 1][1], Ah[kt][2], Al[kt][2]);
        bsplit2(H[2 * kt + 1][2], H[2 * kt + 1][3], Ah[kt][3], Al[kt][3]);
    }
}

__global__ void __launch_bounds__(512, 1) mlp_kernel(const float* __restrict__ ef, float cs) {
    extern __shared__ uint4 sB[];    // 7424 uint4 = 118784 B
    int t = threadIdx.x;
    for (int i = t; i < 7424; i += 512) sB[i] = g_wfragB[i];
    __syncthreads();
    int warp = t >> 5, lane = t & 31, g = lane >> 2, tg = lane & 3;
    int base = (blockIdx.x * 16 + warp) * 16;

    float H[8][4];
    // ---- layer 1 (8 -> 64), K padded to 16 with zeros ----
    {
        unsigned Ah[4], Al[4];
        float2 x0 = *(const float2*)&ef[(base + g) * 8 + 2 * tg];
        float2 x1 = *(const float2*)&ef[(base + g + 8) * 8 + 2 * tg];
        bsplit2(x0.x, x0.y, Ah[0], Al[0]);
        bsplit2(x1.x, x1.y, Ah[1], Al[1]);
        Ah[2] = Al[2] = Ah[3] = Al[3] = 0u;
#pragma unroll
        for (int nt = 0; nt < 8; nt++) {
            float C[4] = {0.f, 0.f, 0.f, 0.f};
            mma3b(C, Ah, Al, sB[nt * 32 + lane]);
#pragma unroll
            for (int i = 0; i < 4; i++) H[nt][i] = silu_n(C[i], cs);
        }
    }
    // ---- layers 2, 3 (64 -> 64) ----
#pragma unroll 1
    for (int l = 0; l < 2; l++) {
        int tb = 8 + l * 32;
        unsigned Ah[4][4], Al[4][4];
        extract_bf(H, Ah, Al);
        float C[8][4];
#pragma unroll
        for (int nt = 0; nt < 8; nt++)
            C[nt][0] = C[nt][1] = C[nt][2] = C[nt][3] = 0.f;
#pragma unroll
        for (int kt = 0; kt < 4; kt++)
#pragma unroll
            for (int nt = 0; nt < 8; nt++)
                mma3b(C[nt], Ah[kt], Al[kt], sB[(tb + kt * 8 + nt) * 32 + lane]);
#pragma unroll
        for (int nt = 0; nt < 8; nt++)
#pragma unroll
            for (int i = 0; i < 4; i++) H[nt][i] = silu_n(C[nt][i], cs);
    }
    // ---- layer 4 (64 -> 320) ----
    {
        unsigned Ah[4][4], Al[4][4];
        extract_bf(H, Ah, Al);
#pragma unroll 1
        for (int chunk = 0; chunk < 5; chunk++) {
            float C[8][4];
#pragma unroll
            for (int nt = 0; nt < 8; nt++)
                C[nt][0] = C[nt][1] = C[nt][2] = C[nt][3] = 0.f;
#pragma unroll
            for (int kt = 0; kt < 4; kt++)
#pragma unroll
                for (int nt = 0; nt < 8; nt++)
                    mma3b(C[nt], Ah[kt], Al[kt], sB[(72 + kt * 40 + chunk * 8 + nt) * 32 + lane]);
#pragma unroll
            for (int nt = 0; nt < 8; nt++) {
                int col = (chunk * 8 + nt) * 8 + 2 * tg;
                *(float2*)&g_tpw[(size_t)(base + g) * 320 + col]     = make_float2(C[nt][0], C[nt][1]);
                *(float2*)&g_tpw[(size_t)(base + g + 8) * 320 + col] = make_float2(C[nt][2], C[nt][3]);
            }
        }
    }
}

// ---------------- msg: warp-per-node gather, zero atomics ----------------
__global__ void __launch_bounds__(256, 1) msg_kernel(const float* __restrict__ ea,
                                                     const int* __restrict__ ie) {
    const float INV_SQRT3 = 0.5773502691896258f;
    const float INV_SQRT2 = 0.7071067811865476f;
    int warp = threadIdx.x >> 5, lane = threadIdx.x & 31;
    int j = blockIdx.x * 8 + warp;
    if (j >= NN) return;
    int off = g_off[j], end = g_off[j + 1];

    float s0x = 0.f, s0y = 0.f, s1x = 0.f, s1y = 0.f;
    float m2a[6] = {0.f, 0.f, 0.f, 0.f, 0.f, 0.f};
    float m3a[6] = {0.f, 0.f, 0.f, 0.f, 0.f, 0.f};
    float m4a[6] = {0.f, 0.f, 0.f, 0.f, 0.f, 0.f};

    for (int k = off; k < end; k++) {
        int e = g_sorted[k];
        int inode = __ldg(&ie[e]);
        float4 e4 = *(const float4*)&ea[e * 4];
        const float* tw = g_tpw + (size_t)e * 320;
        const float* su = g_s_up + inode * 64;
        const float* vu = g_v_up + inode * 192;

        float2 twa = ((const float2*)tw)[lane];
        float2 sua = ((const float2*)su)[lane];
        s0x = fmaf(twa.x * sua.x, e4.x, s0x);
        s0y = fmaf(twa.y * sua.y, e4.x, s0y);

        float2 q0 = ((const float2*)vu)[3 * lane];
        float2 q1 = ((const float2*)vu)[3 * lane + 1];
        float2 q2 = ((const float2*)vu)[3 * lane + 2];
        float2 twb = ((const float2*)(tw + 64))[lane];
        float d0 = q0.x * e4.y + q0.y * e4.z + q1.x * e4.w;
        float d1 = q1.y * e4.y + q2.x * e4.z + q2.y * e4.w;
        s1x = fmaf(twb.x, d0, s1x);
        s1y = fmaf(twb.y, d1, s1y);

        float2 twc = ((const float2*)(tw + 128))[lane];
        float t0 = twc.x * sua.x, t1 = twc.y * sua.y;
        m2a[0] = fmaf(t0, e4.y, m2a[0]); m2a[1] = fmaf(t0, e4.z, m2a[1]); m2a[2] = fmaf(t0, e4.w, m2a[2]);
        m2a[3] = fmaf(t1, e4.y, m2a[3]); m2a[4] = fmaf(t1, e4.z, m2a[4]); m2a[5] = fmaf(t1, e4.w, m2a[5]);

        float2 twd = ((const float2*)(tw + 192))[lane];
        float w0 = twd.x * e4.x, w1 = twd.y * e4.x;
        m3a[0] = fmaf(w0, q0.x, m3a[0]); m3a[1] = fmaf(w0, q0.y, m3a[1]); m3a[2] = fmaf(w0, q1.x, m3a[2]);
        m3a[3] = fmaf(w1, q1.y, m3a[3]); m3a[4] = fmaf(w1, q2.x, m3a[4]); m3a[5] = fmaf(w1, q2.y, m3a[5]);

        float2 twe = ((const float2*)(tw + 256))[lane];
        m4a[0] = fmaf(twe.x, q0.y * e4.w - q1.x * e4.z, m4a[0]);
        m4a[1] = fmaf(twe.x, q1.x * e4.y - q0.x * e4.w, m4a[1]);
        m4a[2] = fmaf(twe.x, q0.x * e4.z - q0.y * e4.y, m4a[2]);
        m4a[3] = fmaf(twe.y, q2.x * e4.w - q2.y * e4.z, m4a[3]);
        m4a[4] = fmaf(twe.y, q2.y * e4.y - q1.y * e4.w, m4a[4]);
        m4a[5] = fmaf(twe.y, q1.y * e4.z - q2.x * e4.y, m4a[5]);
    }

    float* ms = g_msg_s + j * 128;
    ((float2*)ms)[lane]        = make_float2(s0x, s0y);
    ((float2*)(ms + 64))[lane] = make_float2(s1x * INV_SQRT3, s1y * INV_SQRT3);
    float* mv = g_msg_v + j * 576;
    float* p2 = mv + 6 * lane;
    ((float2*)p2)[0] = make_float2(m2a[0], m2a[1]);
    ((float2*)p2)[1] = make_float2(m2a[2], m2a[3]);
    ((float2*)p2)[2] = make_float2(m2a[4], m2a[5]);
    float* p3 = mv + 192 + 6 * lane;
    ((float2*)p3)[0] = make_float2(m3a[0], m3a[1]);
    ((float2*)p3)[1] = make_float2(m3a[2], m3a[3]);
    ((float2*)p3)[2] = make_float2(m3a[4], m3a[5]);
    float* p4 = mv + 384 + 6 * lane;
    ((float2*)p4)[0] = make_float2(m4a[0] * INV_SQRT2, m4a[1] * INV_SQRT2);
    ((float2*)p4)[1] = make_float2(m4a[2] * INV_SQRT2, m4a[3] * INV_SQRT2);
    ((float2*)p4)[2] = make_float2(m4a[4] * INV_SQRT2, m4a[5] * INV_SQRT2);
}

// ---------------- finalize: 2-node register blocking ----------------
__global__ void __launch_bounds__(512, 1) finalize_kernel(
    const float* __restrict__ Wl0, const float* __restrict__ Wl1,
    const float* __restrict__ Ws0c1, const float* __restrict__ Ws0c2,
    const float* __restrict__ Ws0c3, const float* __restrict__ Ws1c1,
    const float* __restrict__ Ws1c2, const float* __restrict__ Ws1c3,
    const float* __restrict__ Wp0, const float* __restrict__ Wp1,
    const int* __restrict__ zn, float* __restrict__ out) {
    const float INV_SQRT3 = 0.5773502691896258f;
    const float INV_SQRT_2C = 0.08838834764831845f;
    const float INV_SQRT_3C = 0.07216878364870323f;
    extern __shared__ float sh[];
    float* sL0 = sh;              // 8192
    float* sL1 = sh + 8192;       // 12288
    float* sP0 = sh + 20480;      // 4096
    float* sP1 = sh + 24576;      // 4096
    float* sT01 = sh + 28672;
    float* sT02 = sh + 29312;
    float* sT03 = sh + 30592;
    float* sT11 = sh + 31872;
    float* sT12 = sh + 32512;
    float* sT13 = sh + 33152;
    float* sDyn = sh + 34432;     // 2 subgroups x 2432

    int t = threadIdx.x;
    for (int i = t; i < 8192; i += 512)  sL0[i] = Wl0[i] * INV_SQRT_2C;
    for (int i = t; i < 12288; i += 512) sL1[i] = Wl1[i] * INV_SQRT_3C;
    for (int i = t; i < 4096; i += 512) { sP0[i] = Wp0[i] * 0.125f; sP1[i] = Wp1[i] * 0.125f; }
    for (int i = t; i < 640; i += 512) { sT01[i] = Ws0c1[i]; sT11[i] = Ws1c1[i]; sT12[i] = Ws1c2[i]; }
    for (int i = t; i < 1280; i += 512) { sT02[i] = Ws0c2[i]; sT03[i] = Ws0c3[i]; sT13[i] = Ws1c3[i]; }
    __syncthreads();

    int sub = t >> 8;
    int tt = t & 255;
    float* st  = sDyn + sub * 2432;
    float* ms  = st;
    float* mv  = st + 256;
    float* v2s = st + 1408;
    float* oss = st + 1792;
    float* cfs = st + 1920;
    float* ovs = st + 2048;

    for (int p = blockIdx.x; p < NN / 4; p += gridDim.x) {
        int n0 = 4 * p + 2 * sub;
        ms[tt] = g_msg_s[(n0 + (tt >> 7)) * 128 + (tt & 127)];
#pragma unroll
        for (int i = 0; i < 5; i++) {
            int idx = i * 256 + tt;
            if (idx < 1152) {
                int nd = idx >= 576;
                mv[idx] = g_msg_v[(n0 + nd) * 576 + (idx - nd * 576)];
            }
        }
        __syncthreads();

        float s2a = 0.f, s2b = 0.f;
        if (tt < 64) {
            int col = tt;
#pragma unroll 8
            for (int c = 0; c < 128; c++) {
                float w = sL0[c * 64 + col];
                s2a = fmaf(ms[c], w, s2a);
                s2b = fmaf(ms[128 + c], w, s2b);
            }
        } else {
            int k = (tt - 64) / 3, m = (tt - 64) - 3 * k;
            float a0 = 0.f, a1 = 0.f;
#pragma unroll 8
            for (int r = 0; r < 192; r++) {
                float w = sL1[r * 64 + k];
                a0 = fmaf(mv[r * 3 + m], w, a0);
                a1 = fmaf(mv[576 + r * 3 + m], w, a1);
            }
            v2s[k * 3 + m] = a0;
            v2s[192 + k * 3 + m] = a1;
        }
        __syncthreads();

        if (tt < 64) {
            int k = tt;
#pragma unroll
            for (int n = 0; n < 2; n++) {
                float s2 = n ? s2b : s2a;
                int z = zn[n0 + n];
                float a = v2s[n * 192 + 3 * k], b = v2s[n * 192 + 3 * k + 1], c = v2s[n * 192 + 3 * k + 2];
                float vv = (a * a + b * b + c * c) * INV_SQRT3;
                float s22 = s2 * s2;
                float outs = sT01[z * 64 + k] * s2 + sT02[(2 * z) * 64 + k] * s22
                           + sT02[(2 * z + 1) * 64 + k] * vv
                           + sT03[(2 * z) * 64 + k] * s22 * s2
                           + sT03[(2 * z + 1) * 64 + k] * s2 * vv;
                float coef = sT11[z * 64 + k] + sT12[z * 64 + k] * s2
                           + sT13[(2 * z) * 64 + k] * s22 + sT13[(2 * z + 1) * 64 + k] * vv;
                oss[n * 64 + k] = outs;
                cfs[n * 64 + k] = coef;
            }
        }
        __syncthreads();
        if (tt >= 64) {
            int idx = tt - 64;
            int k = idx / 3;
            ovs[idx]       = cfs[k] * v2s[idx];
            ovs[192 + idx] = cfs[64 + k] * v2s[192 + idx];
        }
        __syncthreads();

        if (tt < 64) {
            float a0 = 0.f, a1 = 0.f;
#pragma unroll 8
            for (int c = 0; c < 64; c++) {
                float w = sP0[c * 64 + tt];
                a0 = fmaf(oss[c], w, a0);
                a1 = fmaf(oss[64 + c], w, a1);
            }
            out[n0 * 256 + tt] = a0;
            out[(n0 + 1) * 256 + tt] = a1;
        } else {
            int idx = tt - 64;
            int k = idx / 3, m = idx - 3 * k;
            float a0 = 0.f, a1 = 0.f;
#pragma unroll 8
            for (int c = 0; c < 64; c++) {
                float w = sP1[c * 64 + k];
                a0 = fmaf(ovs[c * 3 + m], w, a0);
                a1 = fmaf(ovs[192 + c * 3 + m], w, a1);
            }
            out[n0 * 256 + 64 + idx] = a0;
            out[(n0 + 1) * 256 + 64 + idx] = a1;
        }
        __syncthreads();
    }
}

// ---------------- host launcher ----------------
extern "C" void kernel_launch(void* const* d_in, const int* in_sizes, int n_in,
                              void* d_out, int out_size) {
    const float* nf   = (const float*)d_in[0];
    const float* ef   = (const float*)d_in[1];
    const float* ea   = (const float*)d_in[2];
    const int*   ie   = (const int*)d_in[3];
    const int*   je   = (const int*)d_in[4];
    const int*   zn   = (const int*)d_in[5];
    const float* Wup0 = (const float*)d_in[6];
    const float* Wup1 = (const float*)d_in[7];
    const float* Wm1  = (const float*)d_in[8];
    const float* Wm2  = (const float*)d_in[9];
    const float* Wm3  = (const float*)d_in[10];
    const float* Wm4  = (const float*)d_in[11];
    const float* Wl0  = (const float*)d_in[12];
    const float* Wl1  = (const float*)d_in[13];
    const float* Ws0c1 = (const float*)d_in[14];
    const float* Ws0c2 = (const float*)d_in[15];
    const float* Ws0c3 = (const float*)d_in[16];
    const float* Ws1c1 = (const float*)d_in[17];
    const float* Ws1c2 = (const float*)d_in[18];
    const float* Ws1c3 = (const float*)d_in[19];
    const float* Wp0  = (const float*)d_in[20];
    const float* Wp1  = (const float*)d_in[21];
    float* out = (float*)d_out;

    // C_SILU via trapezoid on R (matches Gauss-Hermite to <1e-7)
    double m2 = 0.0;
    const double hstep = 1.0 / 128.0;
    for (int i = -14 * 128; i <= 14 * 128; i++) {
        double z = i * hstep;
        double f = z / (1.0 + exp(-z));
        m2 += exp(-0.5 * z * z) * f * f;
    }
    m2 *= hstep / sqrt(2.0 * 3.141592653589793);
    float cs = (float)(1.0 / sqrt(m2));

    cudaFuncSetAttribute(mlp_kernel, cudaFuncAttributeMaxDynamicSharedMemorySize, 118784);
    cudaFuncSetAttribute(finalize_kernel, cudaFuncAttributeMaxDynamicSharedMemorySize, 157184);

    node_up_kernel<<<2500, 256>>>(nf, Wup0, Wup1);
    zero_idx_kernel<<<79, 256>>>();
    hist_kernel<<<1250, 256>>>(je);
    scan_kernel<<<1, 1024>>>();
    scatter_kernel<<<1250, 256>>>(je);
    wprep_kernel<<<29, 256>>>(Wm1, Wm2, Wm3, Wm4);
    mlp_kernel<<<1250, 512, 118784>>>(ef, cs);
    msg_kernel<<<2500, 256>>>(ea, ie);
    finalize_kernel<<<296, 512, 157184>>>(Wl0, Wl1, Ws0c1, Ws0c2, Ws0c3,
                                          Ws1c1, Ws1c2, Ws1c3, Wp0, Wp1, zn, out);
}

// round 6
// speedup vs baseline: 1.6931x; 1.0640x over previous
#include <cuda_runtime.h>
#include <math.h>

#define NN    20000
#define NEDGE 320000

// ---------------- device scratch (static, no allocs) ----------------
__device__ __align__(16) float g_s_up[NN * 64];
__device__ __align__(16) float g_v_up[NN * 192];
__device__ __align__(16) float g_msg_s[NN * 128];
__device__ __align__(16) float g_msg_v[NN * 576];           // packed [n][row*3+m]
__device__ __align__(16) float g_tpw[(size_t)NEDGE * 320];  // MLP out, SORTED edge order
__device__ uint4 g_wfragB[7424];                            // bf16 hi/lo weight frags
__device__ int g_deg[NN];
__device__ int g_cursor[NN];
__device__ int g_off[NN + 1];
__device__ int g_sorted[NEDGE];
__device__ int g_ie_s[NEDGE];                               // ie in sorted order
__device__ __align__(16) float g_ea_s[NEDGE * 4];           // ea in sorted order

__device__ __forceinline__ float silu_n(float y, float cs) {
    return cs * y * (1.f / (1.f + __expf(-y)));
}
// pack (x0,x1) into bf16x2 hi part h (x0 low half) and residual lo part l
__device__ __forceinline__ void bsplit2(float x0, float x1, unsigned& h, unsigned& l) {
    asm("cvt.rn.bf16x2.f32 %0, %1, %2;" : "=r"(h) : "f"(x1), "f"(x0));
    float f0 = __uint_as_float(h << 16);
    float f1 = __uint_as_float(h & 0xffff0000u);
    asm("cvt.rn.bf16x2.f32 %0, %1, %2;" : "=r"(l) : "f"(x1 - f1), "f"(x0 - f0));
}
__device__ __forceinline__ void mma16(float* c, const unsigned* a, unsigned b0, unsigned b1) {
    asm volatile("mma.sync.aligned.m16n8k16.row.col.f32.bf16.bf16.f32 "
                 "{%0,%1,%2,%3}, {%4,%5,%6,%7}, {%8,%9}, {%0,%1,%2,%3};"
                 : "+f"(c[0]), "+f"(c[1]), "+f"(c[2]), "+f"(c[3])
                 : "r"(a[0]), "r"(a[1]), "r"(a[2]), "r"(a[3]), "r"(b0), "r"(b1));
}
__device__ __forceinline__ void mma3b(float* c, const unsigned* ah, const unsigned* al, uint4 b) {
    mma16(c, ah, b.x, b.y);
    mma16(c, ah, b.z, b.w);
    mma16(c, al, b.x, b.y);
}

// ---------------- kernel A: node up-projection ----------------
__global__ void node_up_kernel(const float* __restrict__ nf,
                               const float* __restrict__ Wup0,
                               const float* __restrict__ Wup1) {
    __shared__ float sW0[4096];
    __shared__ float sW1[4096];
    __shared__ float sIn[256];
    int t = threadIdx.x;
    for (int i = t; i < 4096; i += 256) {
        sW0[i] = Wup0[i] * 0.125f;
        sW1[i] = Wup1[i] * 0.125f;
    }
    __syncthreads();
    int base = blockIdx.x * 8;
    for (int nn = 0; nn < 8; nn++) {
        int n = base + nn;
        sIn[t] = nf[n * 256 + t];
        __syncthreads();
        if (t < 64) {
            float acc = 0.f;
#pragma unroll 16
            for (int c = 0; c < 64; c++) acc = fmaf(sIn[c], sW0[c * 64 + t], acc);
            g_s_up[n * 64 + t] = acc;
        } else {
            int k = (t - 64) / 3, m = (t - 64) - 3 * k;
            float acc = 0.f;
#pragma unroll 16
            for (int c = 0; c < 64; c++) acc = fmaf(sIn[64 + c * 3 + m], sW1[c * 64 + k], acc);
            g_v_up[n * 192 + k * 3 + m] = acc;
        }
        __syncthreads();
    }
}

// ---------------- destination-sort infrastructure ----------------
__global__ void zero_idx_kernel() {
    int i = blockIdx.x * 256 + threadIdx.x;
    if (i < NN) { g_deg[i] = 0; g_cursor[i] = 0; }
}
__global__ void hist_kernel(const int* __restrict__ je) {
    int i = blockIdx.x * 256 + threadIdx.x;
    if (i < NEDGE) atomicAdd(&g_deg[je[i]], 1);
}
__global__ void scan_kernel() {
    __shared__ int partial[1024];
    int t = threadIdx.x;
    int base = t * 20;
    int cnt[20];
    int sum = 0;
#pragma unroll
    for (int i = 0; i < 20; i++) {
        int v = (base + i < NN) ? g_deg[base + i] : 0;
        cnt[i] = v; sum += v;
    }
    partial[t] = sum;
    __syncthreads();
    for (int s = 1; s < 1024; s <<= 1) {
        int v = (t >= s) ? partial[t - s] : 0;
        __syncthreads();
        partial[t] += v;
        __syncthreads();
    }
    int run = (t == 0) ? 0 : partial[t - 1];
#pragma unroll
    for (int i = 0; i < 20; i++) {
        if (base + i < NN) g_off[base + i] = run;
        run += cnt[i];
    }
    if (t == 1023) g_off[NN] = run;
}
__global__ void scatter_kernel(const int* __restrict__ je, const int* __restrict__ ie,
                               const float* __restrict__ ea) {
    int i = blockIdx.x * 256 + threadIdx.x;
    if (i < NEDGE) {
        int j = je[i];
        int p = atomicAdd(&g_cursor[j], 1);
        int pos = g_off[j] + p;
        g_sorted[pos] = i;
        g_ie_s[pos] = ie[i];
        ((float4*)g_ea_s)[pos] = ((const float4*)ea)[i];
    }
}

// ---------------- weight fragment prep: bf16 hi/lo, prescaled ----------------
__global__ void wprep_kernel(const float* __restrict__ W1, const float* __restrict__ W2,
                             const float* __restrict__ W3, const float* __restrict__ W4) {
    int p = blockIdx.x * blockDim.x + threadIdx.x;
    if (p >= 7424) return;
    int tile = p >> 5, lane = p & 31;
    int g = lane >> 2, tg = lane & 3;
    const float* W; int Ncols, Krows, kt, nglob; float scale;
    if (tile < 8)       { W = W1; Ncols = 64;  Krows = 8;  kt = 0; nglob = tile * 8 + g; scale = 0.3535533905932738f; }
    else if (tile < 40) { W = W2; Ncols = 64;  Krows = 64; int off = tile - 8;  kt = off >> 3; nglob = (off & 7) * 8 + g; scale = 0.125f; }
    else if (tile < 72) { W = W3; Ncols = 64;  Krows = 64; int off = tile - 40; kt = off >> 3; nglob = (off & 7) * 8 + g; scale = 0.125f; }
    else                { W = W4; Ncols = 320; Krows = 64; int off = tile - 72; kt = off / 40; nglob = (off % 40) * 8 + g; scale = 0.125f; }
    int k0 = kt * 16 + 2 * tg;
    float w0 = (k0     < Krows) ? W[(k0)     * Ncols + nglob] * scale : 0.f;
    float w1 = (k0 + 1 < Krows) ? W[(k0 + 1) * Ncols + nglob] * scale : 0.f;
    float w2 = (k0 + 8 < Krows) ? W[(k0 + 8) * Ncols + nglob] * scale : 0.f;
    float w3 = (k0 + 9 < Krows) ? W[(k0 + 9) * Ncols + nglob] * scale : 0.f;
    unsigned h0, l0, h1, l1;
    bsplit2(w0, w1, h0, l0);
    bsplit2(w2, w3, h1, l1);
    g_wfragB[p] = make_uint4(h0, h1, l0, l1);
}

// ---------------- edge MLP: bf16x3, sorted-order in/out ----------------
__device__ __forceinline__ void extract_bf(const float H[8][4], unsigned Ah[4][4], unsigned Al[4][4]) {
#pragma unroll
    for (int kt = 0; kt < 4; kt++) {
        bsplit2(H[2 * kt][0],     H[2 * kt][1],     Ah[kt][0], Al[kt][0]);
        bsplit2(H[2 * kt][2],     H[2 * kt][3],     Ah[kt][1], Al[kt][1]);
        bsplit2(H[2 * kt + 1][0], H[2 * kt + 1][1], Ah[kt][2], Al[kt][2]);
        bsplit2(H[2 * kt + 1][2], H[2 * kt + 1][3], Ah[kt][3], Al[kt][3]);
    }
}

__global__ void __launch_bounds__(512, 1) mlp_kernel(const float* __restrict__ ef, float cs) {
    extern __shared__ uint4 sB[];    // 7424 uint4 = 118784 B
    int t = threadIdx.x;
    for (int i = t; i < 7424; i += 512) sB[i] = g_wfragB[i];
    __syncthreads();
    int warp = t >> 5, lane = t & 31, g = lane >> 2, tg = lane & 3;
    int base = (blockIdx.x * 16 + warp) * 16;
    int eA = g_sorted[base + g];
    int eB = g_sorted[base + g + 8];

    float H[8][4];
    // ---- layer 1 (8 -> 64), K padded to 16 ----
    {
        unsigned Ah[4], Al[4];
        float2 x0 = *(const float2*)&ef[eA * 8 + 2 * tg];
        float2 x1 = *(const float2*)&ef[eB * 8 + 2 * tg];
        bsplit2(x0.x, x0.y, Ah[0], Al[0]);
        bsplit2(x1.x, x1.y, Ah[1], Al[1]);
        Ah[2] = Al[2] = Ah[3] = Al[3] = 0u;
#pragma unroll
        for (int nt = 0; nt < 8; nt++) {
            float C[4] = {0.f, 0.f, 0.f, 0.f};
            mma3b(C, Ah, Al, sB[nt * 32 + lane]);
#pragma unroll
            for (int i = 0; i < 4; i++) H[nt][i] = silu_n(C[i], cs);
        }
    }
    // ---- layers 2, 3 (64 -> 64) ----
#pragma unroll 1
    for (int l = 0; l < 2; l++) {
        int tb = 8 + l * 32;
        unsigned Ah[4][4], Al[4][4];
        extract_bf(H, Ah, Al);
        float C[8][4];
#pragma unroll
        for (int nt = 0; nt < 8; nt++)
            C[nt][0] = C[nt][1] = C[nt][2] = C[nt][3] = 0.f;
#pragma unroll
        for (int kt = 0; kt < 4; kt++)
#pragma unroll
            for (int nt = 0; nt < 8; nt++)
                mma3b(C[nt], Ah[kt], Al[kt], sB[(tb + kt * 8 + nt) * 32 + lane]);
#pragma unroll
        for (int nt = 0; nt < 8; nt++)
#pragma unroll
            for (int i = 0; i < 4; i++) H[nt][i] = silu_n(C[nt][i], cs);
    }
    // ---- layer 4 (64 -> 320), write at SORTED position (sequential) ----
    {
        unsigned Ah[4][4], Al[4][4];
        extract_bf(H, Ah, Al);
#pragma unroll 1
        for (int chunk = 0; chunk < 5; chunk++) {
            float C[8][4];
#pragma unroll
            for (int nt = 0; nt < 8; nt++)
                C[nt][0] = C[nt][1] = C[nt][2] = C[nt][3] = 0.f;
#pragma unroll
            for (int kt = 0; kt < 4; kt++)
#pragma unroll
                for (int nt = 0; nt < 8; nt++)
                    mma3b(C[nt], Ah[kt], Al[kt], sB[(72 + kt * 40 + chunk * 8 + nt) * 32 + lane]);
#pragma unroll
            for (int nt = 0; nt < 8; nt++) {
                int col = (chunk * 8 + nt) * 8 + 2 * tg;
                *(float2*)&g_tpw[(size_t)(base + g) * 320 + col]     = make_float2(C[nt][0], C[nt][1]);
                *(float2*)&g_tpw[(size_t)(base + g + 8) * 320 + col] = make_float2(C[nt][2], C[nt][3]);
            }
        }
    }
}

// ---------------- msg: warp-per-node gather, fully streaming tpw/ie/ea ----------------
__global__ void __launch_bounds__(256, 1) msg_kernel() {
    const float INV_SQRT3 = 0.5773502691896258f;
    const float INV_SQRT2 = 0.7071067811865476f;
    int warp = threadIdx.x >> 5, lane = threadIdx.x & 31;
    int j = blockIdx.x * 8 + warp;
    if (j >= NN) return;
    int off = g_off[j], end = g_off[j + 1];

    float s0x = 0.f, s0y = 0.f, s1x = 0.f, s1y = 0.f;
    float m2a[6] = {0.f, 0.f, 0.f, 0.f, 0.f, 0.f};
    float m3a[6] = {0.f, 0.f, 0.f, 0.f, 0.f, 0.f};
    float m4a[6] = {0.f, 0.f, 0.f, 0.f, 0.f, 0.f};

    for (int k = off; k < end; k++) {
        int inode = __ldg(&g_ie_s[k]);
        float4 e4 = *(const float4*)&g_ea_s[k * 4];
        const float* tw = g_tpw + (size_t)k * 320;
        const float* su = g_s_up + inode * 64;
        const float* vu = g_v_up + inode * 192;

        float2 twa = ((const float2*)tw)[lane];
        float2 sua = ((const float2*)su)[lane];
        s0x = fmaf(twa.x * sua.x, e4.x, s0x);
        s0y = fmaf(twa.y * sua.y, e4.x, s0y);

        float2 q0 = ((const float2*)vu)[3 * lane];
        float2 q1 = ((const float2*)vu)[3 * lane + 1];
        float2 q2 = ((const float2*)vu)[3 * lane + 2];
        float2 twb = ((const float2*)(tw + 64))[lane];
        float d0 = q0.x * e4.y + q0.y * e4.z + q1.x * e4.w;
        float d1 = q1.y * e4.y + q2.x * e4.z + q2.y * e4.w;
        s1x = fmaf(twb.x, d0, s1x);
        s1y = fmaf(twb.y, d1, s1y);

        float2 twc = ((const float2*)(tw + 128))[lane];
        float t0 = twc.x * sua.x, t1 = twc.y * sua.y;
        m2a[0] = fmaf(t0, e4.y, m2a[0]); m2a[1] = fmaf(t0, e4.z, m2a[1]); m2a[2] = fmaf(t0, e4.w, m2a[2]);
        m2a[3] = fmaf(t1, e4.y, m2a[3]); m2a[4] = fmaf(t1, e4.z, m2a[4]); m2a[5] = fmaf(t1, e4.w, m2a[5]);

        float2 twd = ((const float2*)(tw + 192))[lane];
        float w0 = twd.x * e4.x, w1 = twd.y * e4.x;
        m3a[0] = fmaf(w0, q0.x, m3a[0]); m3a[1] = fmaf(w0, q0.y, m3a[1]); m3a[2] = fmaf(w0, q1.x, m3a[2]);
        m3a[3] = fmaf(w1, q1.y, m3a[3]); m3a[4] = fmaf(w1, q2.x, m3a[4]); m3a[5] = fmaf(w1, q2.y, m3a[5]);

        float2 twe = ((const float2*)(tw + 256))[lane];
        m4a[0] = fmaf(twe.x, q0.y * e4.w - q1.x * e4.z, m4a[0]);
        m4a[1] = fmaf(twe.x, q1.x * e4.y - q0.x * e4.w, m4a[1]);
        m4a[2] = fmaf(twe.x, q0.x * e4.z - q0.y * e4.y, m4a[2]);
        m4a[3] = fmaf(twe.y, q2.x * e4.w - q2.y * e4.z, m4a[3]);
        m4a[4] = fmaf(twe.y, q2.y * e4.y - q1.y * e4.w, m4a[4]);
        m4a[5] = fmaf(twe.y, q1.y * e4.z - q2.x * e4.y, m4a[5]);
    }

    float* ms = g_msg_s + j * 128;
    ((float2*)ms)[lane]        = make_float2(s0x, s0y);
    ((float2*)(ms + 64))[lane] = make_float2(s1x * INV_SQRT3, s1y * INV_SQRT3);
    float* mv = g_msg_v + j * 576;
    float* p2 = mv + 6 * lane;
    ((float2*)p2)[0] = make_float2(m2a[0], m2a[1]);
    ((float2*)p2)[1] = make_float2(m2a[2], m2a[3]);
    ((float2*)p2)[2] = make_float2(m2a[4], m2a[5]);
    float* p3 = mv + 192 + 6 * lane;
    ((float2*)p3)[0] = make_float2(m3a[0], m3a[1]);
    ((float2*)p3)[1] = make_float2(m3a[2], m3a[3]);
    ((float2*)p3)[2] = make_float2(m3a[4], m3a[5]);
    float* p4 = mv + 384 + 6 * lane;
    ((float2*)p4)[0] = make_float2(m4a[0] * INV_SQRT2, m4a[1] * INV_SQRT2);
    ((float2*)p4)[1] = make_float2(m4a[2] * INV_SQRT2, m4a[3] * INV_SQRT2);
    ((float2*)p4)[2] = make_float2(m4a[4] * INV_SQRT2, m4a[5] * INV_SQRT2);
}

// ---------------- finalize: 4-node register blocking ----------------
__global__ void __launch_bounds__(512, 1) finalize_kernel(
    const float* __restrict__ Wl0, const float* __restrict__ Wl1,
    const float* __restrict__ Ws0c1, const float* __restrict__ Ws0c2,
    const float* __restrict__ Ws0c3, const float* __restrict__ Ws1c1,
    const float* __restrict__ Ws1c2, const float* __restrict__ Ws1c3,
    const float* __restrict__ Wp0, const float* __restrict__ Wp1,
    const int* __restrict__ zn, float* __restrict__ out) {
    const float INV_SQRT3 = 0.5773502691896258f;
    const float INV_SQRT_2C = 0.08838834764831845f;
    const float INV_SQRT_3C = 0.07216878364870323f;
    extern __shared__ float sh[];
    float* sL0 = sh;              // 8192
    float* sL1 = sh + 8192;       // 12288
    float* sP0 = sh + 20480;      // 4096
    float* sP1 = sh + 24576;      // 4096
    float* sT01 = sh + 28672;     // 640
    float* sT02 = sh + 29312;     // 1280
    float* sT03 = sh + 30592;     // 1280
    float* sT11 = sh + 31872;     // 640
    float* sT12 = sh + 32512;     // 640
    float* sT13 = sh + 33152;     // 1280
    float* sDyn = sh + 34432;     // 2 subgroups x 4864

    int t = threadIdx.x;
    for (int i = t; i < 8192; i += 512)  sL0[i] = Wl0[i] * INV_SQRT_2C;
    for (int i = t; i < 12288; i += 512) sL1[i] = Wl1[i] * INV_SQRT_3C;
    for (int i = t; i < 4096; i += 512) { sP0[i] = Wp0[i] * 0.125f; sP1[i] = Wp1[i] * 0.125f; }
    for (int i = t; i < 640; i += 512) { sT01[i] = Ws0c1[i]; sT11[i] = Ws1c1[i]; sT12[i] = Ws1c2[i]; }
    for (int i = t; i < 1280; i += 512) { sT02[i] = Ws0c2[i]; sT03[i] = Ws0c3[i]; sT13[i] = Ws1c3[i]; }
    __syncthreads();

    int sub = t >> 8;
    int tt = t & 255;
    float* st  = sDyn + sub * 4864;
    float* ms  = st;           // [4][128]
    float* mv  = st + 512;     // [4][576]
    float* v2s = st + 2816;    // [4][192]
    float* oss = st + 3584;    // [4][64]
    float* cfs = st + 3840;    // [4][64]
    float* ovs = st + 4096;    // [4][192]

    for (int p = blockIdx.x; p < NN / 8; p += gridDim.x) {
        int n0 = 8 * p + 4 * sub;
        // stage messages for 4 nodes
#pragma unroll
        for (int i = 0; i < 2; i++) {
            int idx = i * 256 + tt;
            ms[idx] = g_msg_s[(n0 + (idx >> 7)) * 128 + (idx & 127)];
        }
#pragma unroll
        for (int i = 0; i < 9; i++) {
            int idx = i * 256 + tt;
            int nd = idx / 576;
            mv[idx] = g_msg_v[(n0 + nd) * 576 + (idx - nd * 576)];
        }
        __syncthreads();

        float s2r[4];
        if (tt < 64) {
            float a0 = 0.f, a1 = 0.f, a2 = 0.f, a3 = 0.f;
#pragma unroll 4
            for (int c = 0; c < 128; c++) {
                float w = sL0[c * 64 + tt];
                a0 = fmaf(ms[c],       w, a0);
                a1 = fmaf(ms[128 + c], w, a1);
                a2 = fmaf(ms[256 + c], w, a2);
                a3 = fmaf(ms[384 + c], w, a3);
            }
            s2r[0] = a0; s2r[1] = a1; s2r[2] = a2; s2r[3] = a3;
        } else {
            int k = (tt - 64) / 3, m = (tt - 64) - 3 * k;
            float a0 = 0.f, a1 = 0.f, a2 = 0.f, a3 = 0.f;
#pragma unroll 4
            for (int r = 0; r < 192; r++) {
                float w = sL1[r * 64 + k];
                int o = r * 3 + m;
                a0 = fmaf(mv[o],        w, a0);
                a1 = fmaf(mv[576 + o],  w, a1);
                a2 = fmaf(mv[1152 + o], w, a2);
                a3 = fmaf(mv[1728 + o], w, a3);
            }
            v2s[k * 3 + m]       = a0;
            v2s[192 + k * 3 + m] = a1;
            v2s[384 + k * 3 + m] = a2;
            v2s[576 + k * 3 + m] = a3;
        }
        __syncthreads();

        if (tt < 64) {
            int k = tt;
#pragma unroll
            for (int n = 0; n < 4; n++) {
                float s2 = s2r[n];
                int z = zn[n0 + n];
                float a = v2s[n * 192 + 3 * k], b = v2s[n * 192 + 3 * k + 1], c = v2s[n * 192 + 3 * k + 2];
                float vv = (a * a + b * b + c * c) * INV_SQRT3;
                float s22 = s2 * s2;
                float outs = sT01[z * 64 + k] * s2 + sT02[(2 * z) * 64 + k] * s22
                           + sT02[(2 * z + 1) * 64 + k] * vv
                           + sT03[(2 * z) * 64 + k] * s22 * s2
                           + sT03[(2 * z + 1) * 64 + k] * s2 * vv;
                float coef = sT11[z * 64 + k] + sT12[z * 64 + k] * s2
                           + sT13[(2 * z) * 64 + k] * s22 + sT13[(2 * z + 1) * 64 + k] * vv;
                oss[n * 64 + k] = outs;
                cfs[n * 64 + k] = coef;
            }
        }
        __syncthreads();
        if (tt >= 64) {
            int idx = tt - 64;
            int k = idx / 3;
#pragma unroll
            for (int n = 0; n < 4; n++)
                ovs[n * 192 + idx] = cfs[n * 64 + k] * v2s[n * 192 + idx];
        }
        __syncthreads();

        if (tt < 64) {
            float a0 = 0.f, a1 = 0.f, a2 = 0.f, a3 = 0.f;
#pragma unroll 4
            for (int c = 0; c < 64; c++) {
                float w = sP0[c * 64 + tt];
                a0 = fmaf(oss[c],       w, a0);
                a1 = fmaf(oss[64 + c],  w, a1);
                a2 = fmaf(oss[128 + c], w, a2);
                a3 = fmaf(oss[192 + c], w, a3);
            }
            out[n0 * 256 + tt]       = a0;
            out[(n0 + 1) * 256 + tt] = a1;
            out[(n0 + 2) * 256 + tt] = a2;
            out[(n0 + 3) * 256 + tt] = a3;
        } else {
            int idx = tt - 64;
            int k = idx / 3, m = idx - 3 * k;
            float a0 = 0.f, a1 = 0.f, a2 = 0.f, a3 = 0.f;
#pragma unroll 4
            for (int c = 0; c < 64; c++) {
                float w = sP1[c * 64 + k];
                int o = c * 3 + m;
                a0 = fmaf(ovs[o],       w, a0);
                a1 = fmaf(ovs[192 + o], w, a1);
                a2 = fmaf(ovs[384 + o], w, a2);
                a3 = fmaf(ovs[576 + o], w, a3);
            }
            out[n0 * 256 + 64 + idx]       = a0;
            out[(n0 + 1) * 256 + 64 + idx] = a1;
            out[(n0 + 2) * 256 + 64 + idx] = a2;
            out[(n0 + 3) * 256 + 64 + idx] = a3;
        }
        __syncthreads();
    }
}

// ---------------- host launcher ----------------
extern "C" void kernel_launch(void* const* d_in, const int* in_sizes, int n_in,
                              void* d_out, int out_size) {
    const float* nf   = (const float*)d_in[0];
    const float* ef   = (const float*)d_in[1];
    const float* ea   = (const float*)d_in[2];
    const int*   ie   = (const int*)d_in[3];
    const int*   je   = (const int*)d_in[4];
    const int*   zn   = (const int*)d_in[5];
    const float* Wup0 = (const float*)d_in[6];
    const float* Wup1 = (const float*)d_in[7];
    const float* Wm1  = (const float*)d_in[8];
    const float* Wm2  = (const float*)d_in[9];
    const float* Wm3  = (const float*)d_in[10];
    const float* Wm4  = (const float*)d_in[11];
    const float* Wl0  = (const float*)d_in[12];
    const float* Wl1  = (const float*)d_in[13];
    const float* Ws0c1 = (const float*)d_in[14];
    const float* Ws0c2 = (const float*)d_in[15];
    const float* Ws0c3 = (const float*)d_in[16];
    const float* Ws1c1 = (const float*)d_in[17];
    const float* Ws1c2 = (const float*)d_in[18];
    const float* Ws1c3 = (const float*)d_in[19];
    const float* Wp0  = (const float*)d_in[20];
    const float* Wp1  = (const float*)d_in[21];
    float* out = (float*)d_out;

    // C_SILU via trapezoid on R (matches Gauss-Hermite to <1e-7)
    double m2 = 0.0;
    const double hstep = 1.0 / 128.0;
    for (int i = -14 * 128; i <= 14 * 128; i++) {
        double z = i * hstep;
        double f = z / (1.0 + exp(-z));
        m2 += exp(-0.5 * z * z) * f * f;
    }
    m2 *= hstep / sqrt(2.0 * 3.141592653589793);
    float cs = (float)(1.0 / sqrt(m2));

    cudaFuncSetAttribute(mlp_kernel, cudaFuncAttributeMaxDynamicSharedMemorySize, 118784);
    cudaFuncSetAttribute(finalize_kernel, cudaFuncAttributeMaxDynamicSharedMemorySize, 176640);

    node_up_kernel<<<2500, 256>>>(nf, Wup0, Wup1);
    zero_idx_kernel<<<79, 256>>>();
    hist_kernel<<<1250, 256>>>(je);
    scan_kernel<<<1, 1024>>>();
    scatter_kernel<<<1250, 256>>>(je, ie, ea);
    wprep_kernel<<<29, 256>>>(Wm1, Wm2, Wm3, Wm4);
    mlp_kernel<<<1250, 512, 118784>>>(ef, cs);
    msg_kernel<<<2500, 256>>>();
    finalize_kernel<<<296, 512, 176640>>>(Wl0, Wl1, Ws0c1, Ws0c2, Ws0c3,
                                          Ws1c1, Ws1c2, Ws1c3, Wp0, Wp1, zn, out);
}

// round 7
// speedup vs baseline: 1.7400x; 1.0277x over previous
#include <cuda_runtime.h>
#include <cuda_fp16.h>
#include <math.h>

#define NN    20000
#define NEDGE 320000

// ---------------- device scratch (static, no allocs) ----------------
__device__ __align__(16) float g_s_up[NN * 64];
__device__ __align__(16) float g_v_up[NN * 192];
__device__ __align__(16) float g_msg_s[NN * 128];
__device__ __align__(16) float g_msg_v[NN * 576];            // packed [n][row*3+m]
__device__ __align__(16) __half g_tpw[(size_t)NEDGE * 320];  // MLP out, SORTED order, fp16
__device__ uint4 g_wfragB[7424];                             // bf16 hi/lo weight frags
__device__ int g_deg[NN];
__device__ int g_cursor[NN];
__device__ int g_off[NN + 1];
__device__ int g_sorted[NEDGE];
__device__ int g_ie_s[NEDGE];                                // ie in sorted order
__device__ __align__(16) float g_ea_s[NEDGE * 4];            // ea in sorted order

__device__ __forceinline__ float silu_n(float y, float cs) {
    return cs * y * (1.f / (1.f + __expf(-y)));
}
// pack (x0,x1) into bf16x2 hi part h (x0 low half) and residual lo part l
__device__ __forceinline__ void bsplit2(float x0, float x1, unsigned& h, unsigned& l) {
    asm("cvt.rn.bf16x2.f32 %0, %1, %2;" : "=r"(h) : "f"(x1), "f"(x0));
    float f0 = __uint_as_float(h << 16);
    float f1 = __uint_as_float(h & 0xffff0000u);
    asm("cvt.rn.bf16x2.f32 %0, %1, %2;" : "=r"(l) : "f"(x1 - f1), "f"(x0 - f0));
}
__device__ __forceinline__ void mma16(float* c, const unsigned* a, unsigned b0, unsigned b1) {
    asm volatile("mma.sync.aligned.m16n8k16.row.col.f32.bf16.bf16.f32 "
                 "{%0,%1,%2,%3}, {%4,%5,%6,%7}, {%8,%9}, {%0,%1,%2,%3};"
                 : "+f"(c[0]), "+f"(c[1]), "+f"(c[2]), "+f"(c[3])
                 : "r"(a[0]), "r"(a[1]), "r"(a[2]), "r"(a[3]), "r"(b0), "r"(b1));
}
__device__ __forceinline__ void mma3b(float* c, const unsigned* ah, const unsigned* al, uint4 b) {
    mma16(c, ah, b.x, b.y);
    mma16(c, ah, b.z, b.w);
    mma16(c, al, b.x, b.y);
}

// ---------------- kernel A: node up-projection ----------------
__global__ void node_up_kernel(const float* __restrict__ nf,
                               const float* __restrict__ Wup0,
                               const float* __restrict__ Wup1) {
    __shared__ float sW0[4096];
    __shared__ float sW1[4096];
    __shared__ float sIn[256];
    int t = threadIdx.x;
    for (int i = t; i < 4096; i += 256) {
        sW0[i] = Wup0[i] * 0.125f;
        sW1[i] = Wup1[i] * 0.125f;
    }
    __syncthreads();
    int base = blockIdx.x * 8;
    for (int nn = 0; nn < 8; nn++) {
        int n = base + nn;
        sIn[t] = nf[n * 256 + t];
        __syncthreads();
        if (t < 64) {
            float acc = 0.f;
#pragma unroll 16
            for (int c = 0; c < 64; c++) acc = fmaf(sIn[c], sW0[c * 64 + t], acc);
            g_s_up[n * 64 + t] = acc;
        } else {
            int k = (t - 64) / 3, m = (t - 64) - 3 * k;
            float acc = 0.f;
#pragma unroll 16
            for (int c = 0; c < 64; c++) acc = fmaf(sIn[64 + c * 3 + m], sW1[c * 64 + k], acc);
            g_v_up[n * 192 + k * 3 + m] = acc;
        }
        __syncthreads();
    }
}

// ---------------- fused: weight fragment prep + index zeroing ----------------
// p < 7424: bf16 hi/lo weight frags; p in [7424, 27424): zero deg/cursor
__global__ void prep_kernel(const float* __restrict__ W1, const float* __restrict__ W2,
                            const float* __restrict__ W3, const float* __restrict__ W4) {
    int p = blockIdx.x * blockDim.x + threadIdx.x;
    if (p >= 7424) {
        int i = p - 7424;
        if (i < NN) { g_deg[i] = 0; g_cursor[i] = 0; }
        return;
    }
    int tile = p >> 5, lane = p & 31;
    int g = lane >> 2, tg = lane & 3;
    const float* W; int Ncols, Krows, kt, nglob; float scale;
    if (tile < 8)       { W = W1; Ncols = 64;  Krows = 8;  kt = 0; nglob = tile * 8 + g; scale = 0.3535533905932738f; }
    else if (tile < 40) { W = W2; Ncols = 64;  Krows = 64; int off = tile - 8;  kt = off >> 3; nglob = (off & 7) * 8 + g; scale = 0.125f; }
    else if (tile < 72) { W = W3; Ncols = 64;  Krows = 64; int off = tile - 40; kt = off >> 3; nglob = (off & 7) * 8 + g; scale = 0.125f; }
    else                { W = W4; Ncols = 320; Krows = 64; int off = tile - 72; kt = off / 40; nglob = (off % 40) * 8 + g; scale = 0.125f; }
    int k0 = kt * 16 + 2 * tg;
    float w0 = (k0     < Krows) ? W[(k0)     * Ncols + nglob] * scale : 0.f;
    float w1 = (k0 + 1 < Krows) ? W[(k0 + 1) * Ncols + nglob] * scale : 0.f;
    float w2 = (k0 + 8 < Krows) ? W[(k0 + 8) * Ncols + nglob] * scale : 0.f;
    float w3 = (k0 + 9 < Krows) ? W[(k0 + 9) * Ncols + nglob] * scale : 0.f;
    unsigned h0, l0, h1, l1;
    bsplit2(w0, w1, h0, l0);
    bsplit2(w2, w3, h1, l1);
    g_wfragB[p] = make_uint4(h0, h1, l0, l1);
}

// ---------------- destination-sort infrastructure ----------------
__global__ void hist_kernel(const int* __restrict__ je) {
    int i = blockIdx.x * 256 + threadIdx.x;
    if (i < NEDGE) atomicAdd(&g_deg[je[i]], 1);
}
__global__ void scan_kernel() {
    __shared__ int partial[1024];
    int t = threadIdx.x;
    int base = t * 20;
    int cnt[20];
    int sum = 0;
#pragma unroll
    for (int i = 0; i < 20; i++) {
        int v = (base + i < NN) ? g_deg[base + i] : 0;
        cnt[i] = v; sum += v;
    }
    partial[t] = sum;
    __syncthreads();
    for (int s = 1; s < 1024; s <<= 1) {
        int v = (t >= s) ? partial[t - s] : 0;
        __syncthreads();
        partial[t] += v;
        __syncthreads();
    }
    int run = (t == 0) ? 0 : partial[t - 1];
#pragma unroll
    for (int i = 0; i < 20; i++) {
        if (base + i < NN) g_off[base + i] = run;
        run += cnt[i];
    }
    if (t == 1023) g_off[NN] = run;
}
__global__ void scatter_kernel(const int* __restrict__ je, const int* __restrict__ ie,
                               const float* __restrict__ ea) {
    int i = blockIdx.x * 256 + threadIdx.x;
    if (i < NEDGE) {
        int j = je[i];
        int p = atomicAdd(&g_cursor[j], 1);
        int pos = g_off[j] + p;
        g_sorted[pos] = i;
        g_ie_s[pos] = ie[i];
        ((float4*)g_ea_s)[pos] = ((const float4*)ea)[i];
    }
}

// ---------------- edge MLP: bf16x3, sorted-order in/out, fp16 tpw ----------------
__device__ __forceinline__ void extract_bf(const float H[8][4], unsigned Ah[4][4], unsigned Al[4][4]) {
#pragma unroll
    for (int kt = 0; kt < 4; kt++) {
        bsplit2(H[2 * kt][0],     H[2 * kt][1],     Ah[kt][0], Al[kt][0]);
        bsplit2(H[2 * kt][2],     H[2 * kt][3],     Ah[kt][1], Al[kt][1]);
        bsplit2(H[2 * kt + 1][0], H[2 * kt + 1][1], Ah[kt][2], Al[kt][2]);
        bsplit2(H[2 * kt + 1][2], H[2 * kt + 1][3], Ah[kt][3], Al[kt][3]);
    }
}

__global__ void __launch_bounds__(512, 1) mlp_kernel(const float* __restrict__ ef, float cs) {
    extern __shared__ uint4 sB[];    // 7424 uint4 = 118784 B
    int t = threadIdx.x;
    for (int i = t; i < 7424; i += 512) sB[i] = g_wfragB[i];
    __syncthreads();
    int warp = t >> 5, lane = t & 31, g = lane >> 2, tg = lane & 3;
    int base = (blockIdx.x * 16 + warp) * 16;
    int eA = g_sorted[base + g];
    int eB = g_sorted[base + g + 8];

    float H[8][4];
    // ---- layer 1 (8 -> 64), K padded to 16 ----
    {
        unsigned Ah[4], Al[4];
        float2 x0 = *(const float2*)&ef[eA * 8 + 2 * tg];
        float2 x1 = *(const float2*)&ef[eB * 8 + 2 * tg];
        bsplit2(x0.x, x0.y, Ah[0], Al[0]);
        bsplit2(x1.x, x1.y, Ah[1], Al[1]);
        Ah[2] = Al[2] = Ah[3] = Al[3] = 0u;
#pragma unroll
        for (int nt = 0; nt < 8; nt++) {
            float C[4] = {0.f, 0.f, 0.f, 0.f};
            mma3b(C, Ah, Al, sB[nt * 32 + lane]);
#pragma unroll
            for (int i = 0; i < 4; i++) H[nt][i] = silu_n(C[i], cs);
        }
    }
    // ---- layers 2, 3 (64 -> 64) ----
#pragma unroll 1
    for (int l = 0; l < 2; l++) {
        int tb = 8 + l * 32;
        unsigned Ah[4][4], Al[4][4];
        extract_bf(H, Ah, Al);
        float C[8][4];
#pragma unroll
        for (int nt = 0; nt < 8; nt++)
            C[nt][0] = C[nt][1] = C[nt][2] = C[nt][3] = 0.f;
#pragma unroll
        for (int kt = 0; kt < 4; kt++)
#pragma unroll
            for (int nt = 0; nt < 8; nt++)
                mma3b(C[nt], Ah[kt], Al[kt], sB[(tb + kt * 8 + nt) * 32 + lane]);
#pragma unroll
        for (int nt = 0; nt < 8; nt++)
#pragma unroll
            for (int i = 0; i < 4; i++) H[nt][i] = silu_n(C[nt][i], cs);
    }
    // ---- layer 4 (64 -> 320), fp16 write at SORTED position (sequential) ----
    {
        unsigned Ah[4][4], Al[4][4];
        extract_bf(H, Ah, Al);
#pragma unroll 1
        for (int chunk = 0; chunk < 5; chunk++) {
            float C[8][4];
#pragma unroll
            for (int nt = 0; nt < 8; nt++)
                C[nt][0] = C[nt][1] = C[nt][2] = C[nt][3] = 0.f;
#pragma unroll
            for (int kt = 0; kt < 4; kt++)
#pragma unroll
                for (int nt = 0; nt < 8; nt++)
                    mma3b(C[nt], Ah[kt], Al[kt], sB[(72 + kt * 40 + chunk * 8 + nt) * 32 + lane]);
#pragma unroll
            for (int nt = 0; nt < 8; nt++) {
                int col = (chunk * 8 + nt) * 8 + 2 * tg;
                *(half2*)&g_tpw[(size_t)(base + g) * 320 + col]     = __floats2half2_rn(C[nt][0], C[nt][1]);
                *(half2*)&g_tpw[(size_t)(base + g + 8) * 320 + col] = __floats2half2_rn(C[nt][2], C[nt][3]);
            }
        }
    }
}

// ---------------- msg: warp-per-node gather, streaming fp16 tpw ----------------
__global__ void __launch_bounds__(512, 1) msg_kernel() {
    const float INV_SQRT3 = 0.5773502691896258f;
    const float INV_SQRT2 = 0.7071067811865476f;
    int warp = threadIdx.x >> 5, lane = threadIdx.x & 31;
    int j = blockIdx.x * 16 + warp;
    if (j >= NN) return;
    int off = g_off[j], end = g_off[j + 1];

    float s0x = 0.f, s0y = 0.f, s1x = 0.f, s1y = 0.f;
    float m2a[6] = {0.f, 0.f, 0.f, 0.f, 0.f, 0.f};
    float m3a[6] = {0.f, 0.f, 0.f, 0.f, 0.f, 0.f};
    float m4a[6] = {0.f, 0.f, 0.f, 0.f, 0.f, 0.f};

#pragma unroll 2
    for (int k = off; k < end; k++) {
        int inode = __ldg(&g_ie_s[k]);
        float4 e4 = *(const float4*)&g_ea_s[k * 4];
        const __half* tw = g_tpw + (size_t)k * 320;
        const float* su = g_s_up + inode * 64;
        const float* vu = g_v_up + inode * 192;

        float2 twa = __half22float2(((const half2*)tw)[lane]);
        float2 sua = ((const float2*)su)[lane];
        s0x = fmaf(twa.x * sua.x, e4.x, s0x);
        s0y = fmaf(twa.y * sua.y, e4.x, s0y);

        float2 q0 = ((const float2*)vu)[3 * lane];
        float2 q1 = ((const float2*)vu)[3 * lane + 1];
        float2 q2 = ((const float2*)vu)[3 * lane + 2];
        float2 twb = __half22float2(((const half2*)(tw + 64))[lane]);
        float d0 = q0.x * e4.y + q0.y * e4.z + q1.x * e4.w;
        float d1 = q1.y * e4.y + q2.x * e4.z + q2.y * e4.w;
        s1x = fmaf(twb.x, d0, s1x);
        s1y = fmaf(twb.y, d1, s1y);

        float2 twc = __half22float2(((const half2*)(tw + 128))[lane]);
        float t0 = twc.x * sua.x, t1 = twc.y * sua.y;
        m2a[0] = fmaf(t0, e4.y, m2a[0]); m2a[1] = fmaf(t0, e4.z, m2a[1]); m2a[2] = fmaf(t0, e4.w, m2a[2]);
        m2a[3] = fmaf(t1, e4.y, m2a[3]); m2a[4] = fmaf(t1, e4.z, m2a[4]); m2a[5] = fmaf(t1, e4.w, m2a[5]);

        float2 twd = __half22float2(((const half2*)(tw + 192))[lane]);
        float w0 = twd.x * e4.x, w1 = twd.y * e4.x;
        m3a[0] = fmaf(w0, q0.x, m3a[0]); m3a[1] = fmaf(w0, q0.y, m3a[1]); m3a[2] = fmaf(w0, q1.x, m3a[2]);
        m3a[3] = fmaf(w1, q1.y, m3a[3]); m3a[4] = fmaf(w1, q2.x, m3a[4]); m3a[5] = fmaf(w1, q2.y, m3a[5]);

        float2 twe = __half22float2(((const half2*)(tw + 256))[lane]);
        m4a[0] = fmaf(twe.x, q0.y * e4.w - q1.x * e4.z, m4a[0]);
        m4a[1] = fmaf(twe.x, q1.x * e4.y - q0.x * e4.w, m4a[1]);
        m4a[2] = fmaf(twe.x, q0.x * e4.z - q0.y * e4.y, m4a[2]);
        m4a[3] = fmaf(twe.y, q2.x * e4.w - q2.y * e4.z, m4a[3]);
        m4a[4] = fmaf(twe.y, q2.y * e4.y - q1.y * e4.w, m4a[4]);
        m4a[5] = fmaf(twe.y, q1.y * e4.z - q2.x * e4.y, m4a[5]);
    }

    float* ms = g_msg_s + j * 128;
    ((float2*)ms)[lane]        = make_float2(s0x, s0y);
    ((float2*)(ms + 64))[lane] = make_float2(s1x * INV_SQRT3, s1y * INV_SQRT3);
    float* mv = g_msg_v + j * 576;
    float* p2 = mv + 6 * lane;
    ((float2*)p2)[0] = make_float2(m2a[0], m2a[1]);
    ((float2*)p2)[1] = make_float2(m2a[2], m2a[3]);
    ((float2*)p2)[2] = make_float2(m2a[4], m2a[5]);
    float* p3 = mv + 192 + 6 * lane;
    ((float2*)p3)[0] = make_float2(m3a[0], m3a[1]);
    ((float2*)p3)[1] = make_float2(m3a[2], m3a[3]);
    ((float2*)p3)[2] = make_float2(m3a[4], m3a[5]);
    float* p4 = mv + 384 + 6 * lane;
    ((float2*)p4)[0] = make_float2(m4a[0] * INV_SQRT2, m4a[1] * INV_SQRT2);
    ((float2*)p4)[1] = make_float2(m4a[2] * INV_SQRT2, m4a[3] * INV_SQRT2);
    ((float2*)p4)[2] = make_float2(m4a[4] * INV_SQRT2, m4a[5] * INV_SQRT2);
}

// ---------------- finalize: 4-node register blocking ----------------
__global__ void __launch_bounds__(512, 1) finalize_kernel(
    const float* __restrict__ Wl0, const float* __restrict__ Wl1,
    const float* __restrict__ Ws0c1, const float* __restrict__ Ws0c2,
    const float* __restrict__ Ws0c3, const float* __restrict__ Ws1c1,
    const float* __restrict__ Ws1c2, const float* __restrict__ Ws1c3,
    const float* __restrict__ Wp0, const float* __restrict__ Wp1,
    const int* __restrict__ zn, float* __restrict__ out) {
    const float INV_SQRT3 = 0.5773502691896258f;
    const float INV_SQRT_2C = 0.08838834764831845f;
    const float INV_SQRT_3C = 0.07216878364870323f;
    extern __shared__ float sh[];
    float* sL0 = sh;              // 8192
    float* sL1 = sh + 8192;       // 12288
    float* sP0 = sh + 20480;      // 4096
    float* sP1 = sh + 24576;      // 4096
    float* sT01 = sh + 28672;     // 640
    float* sT02 = sh + 29312;     // 1280
    float* sT03 = sh + 30592;     // 1280
    float* sT11 = sh + 31872;     // 640
    float* sT12 = sh + 32512;     // 640
    float* sT13 = sh + 33152;     // 1280
    float* sDyn = sh + 34432;     // 2 subgroups x 4864

    int t = threadIdx.x;
    for (int i = t; i < 8192; i += 512)  sL0[i] = Wl0[i] * INV_SQRT_2C;
    for (int i = t; i < 12288; i += 512) sL1[i] = Wl1[i] * INV_SQRT_3C;
    for (int i = t; i < 4096; i += 512) { sP0[i] = Wp0[i] * 0.125f; sP1[i] = Wp1[i] * 0.125f; }
    for (int i = t; i < 640; i += 512) { sT01[i] = Ws0c1[i]; sT11[i] = Ws1c1[i]; sT12[i] = Ws1c2[i]; }
    for (int i = t; i < 1280; i += 512) { sT02[i] = Ws0c2[i]; sT03[i] = Ws0c3[i]; sT13[i] = Ws1c3[i]; }
    __syncthreads();

    int sub = t >> 8;
    int tt = t & 255;
    float* st  = sDyn + sub * 4864;
    float* ms  = st;           // [4][128]
    float* mv  = st + 512;     // [4][576]
    float* v2s = st + 2816;    // [4][192]
    float* oss = st + 3584;    // [4][64]
    float* cfs = st + 3840;    // [4][64]
    float* ovs = st + 4096;    // [4][192]

    for (int p = blockIdx.x; p < NN / 8; p += gridDim.x) {
        int n0 = 8 * p + 4 * sub;
#pragma unroll
        for (int i = 0; i < 2; i++) {
            int idx = i * 256 + tt;
            ms[idx] = g_msg_s[(n0 + (idx >> 7)) * 128 + (idx & 127)];
        }
#pragma unroll
        for (int i = 0; i < 9; i++) {
            int idx = i * 256 + tt;
            int nd = idx / 576;
            mv[idx] = g_msg_v[(n0 + nd) * 576 + (idx - nd * 576)];
        }
        __syncthreads();

        float s2r[4];
        if (tt < 64) {
            float a0 = 0.f, a1 = 0.f, a2 = 0.f, a3 = 0.f;
#pragma unroll 4
            for (int c = 0; c < 128; c++) {
                float w = sL0[c * 64 + tt];
                a0 = fmaf(ms[c],       w, a0);
                a1 = fmaf(ms[128 + c], w, a1);
                a2 = fmaf(ms[256 + c], w, a2);
                a3 = fmaf(ms[384 + c], w, a3);
            }
            s2r[0] = a0; s2r[1] = a1; s2r[2] = a2; s2r[3] = a3;
        } else {
            int k = (tt - 64) / 3, m = (tt - 64) - 3 * k;
            float a0 = 0.f, a1 = 0.f, a2 = 0.f, a3 = 0.f;
#pragma unroll 4
            for (int r = 0; r < 192; r++) {
                float w = sL1[r * 64 + k];
                int o = r * 3 + m;
                a0 = fmaf(mv[o],        w, a0);
                a1 = fmaf(mv[576 + o],  w, a1);
                a2 = fmaf(mv[1152 + o], w, a2);
                a3 = fmaf(mv[1728 + o], w, a3);
            }
            v2s[k * 3 + m]       = a0;
            v2s[192 + k * 3 + m] = a1;
            v2s[384 + k * 3 + m] = a2;
            v2s[576 + k * 3 + m] = a3;
        }
        __syncthreads();

        if (tt < 64) {
            int k = tt;
#pragma unroll
            for (int n = 0; n < 4; n++) {
                float s2 = s2r[n];
                int z = zn[n0 + n];
                float a = v2s[n * 192 + 3 * k], b = v2s[n * 192 + 3 * k + 1], c = v2s[n * 192 + 3 * k + 2];
                float vv = (a * a + b * b + c * c) * INV_SQRT3;
                float s22 = s2 * s2;
                float outs = sT01[z * 64 + k] * s2 + sT02[(2 * z) * 64 + k] * s22
                           + sT02[(2 * z + 1) * 64 + k] * vv
                           + sT03[(2 * z) * 64 + k] * s22 * s2
                           + sT03[(2 * z + 1) * 64 + k] * s2 * vv;
                float coef = sT11[z * 64 + k] + sT12[z * 64 + k] * s2
                           + sT13[(2 * z) * 64 + k] * s22 + sT13[(2 * z + 1) * 64 + k] * vv;
                oss[n * 64 + k] = outs;
                cfs[n * 64 + k] = coef;
            }
        }
        __syncthreads();
        if (tt >= 64) {
            int idx = tt - 64;
            int k = idx / 3;
#pragma unroll
            for (int n = 0; n < 4; n++)
                ovs[n * 192 + idx] = cfs[n * 64 + k] * v2s[n * 192 + idx];
        }
        __syncthreads();

        if (tt < 64) {
            float a0 = 0.f, a1 = 0.f, a2 = 0.f, a3 = 0.f;
#pragma unroll 4
            for (int c = 0; c < 64; c++) {
                float w = sP0[c * 64 + tt];
                a0 = fmaf(oss[c],       w, a0);
                a1 = fmaf(oss[64 + c],  w, a1);
                a2 = fmaf(oss[128 + c], w, a2);
                a3 = fmaf(oss[192 + c], w, a3);
            }
            out[n0 * 256 + tt]       = a0;
            out[(n0 + 1) * 256 + tt] = a1;
            out[(n0 + 2) * 256 + tt] = a2;
            out[(n0 + 3) * 256 + tt] = a3;
        } else {
            int idx = tt - 64;
            int k = idx / 3, m = idx - 3 * k;
            float a0 = 0.f, a1 = 0.f, a2 = 0.f, a3 = 0.f;
#pragma unroll 4
            for (int c = 0; c < 64; c++) {
                float w = sP1[c * 64 + k];
                int o = c * 3 + m;
                a0 = fmaf(ovs[o],       w, a0);
                a1 = fmaf(ovs[192 + o], w, a1);
                a2 = fmaf(ovs[384 + o], w, a2);
                a3 = fmaf(ovs[576 + o], w, a3);
            }
            out[n0 * 256 + 64 + idx]       = a0;
            out[(n0 + 1) * 256 + 64 + idx] = a1;
            out[(n0 + 2) * 256 + 64 + idx] = a2;
            out[(n0 + 3) * 256 + 64 + idx] = a3;
        }
        __syncthreads();
    }
}

// ---------------- host launcher ----------------
extern "C" void kernel_launch(void* const* d_in, const int* in_sizes, int n_in,
                              void* d_out, int out_size) {
    const float* nf   = (const float*)d_in[0];
    const float* ef   = (const float*)d_in[1];
    const float* ea   = (const float*)d_in[2];
    const int*   ie   = (const int*)d_in[3];
    const int*   je   = (const int*)d_in[4];
    const int*   zn   = (const int*)d_in[5];
    const float* Wup0 = (const float*)d_in[6];
    const float* Wup1 = (const float*)d_in[7];
    const float* Wm1  = (const float*)d_in[8];
    const float* Wm2  = (const float*)d_in[9];
    const float* Wm3  = (const float*)d_in[10];
    const float* Wm4  = (const float*)d_in[11];
    const float* Wl0  = (const float*)d_in[12];
    const float* Wl1  = (const float*)d_in[13];
    const float* Ws0c1 = (const float*)d_in[14];
    const float* Ws0c2 = (const float*)d_in[15];
    const float* Ws0c3 = (const float*)d_in[16];
    const float* Ws1c1 = (const float*)d_in[17];
    const float* Ws1c2 = (const float*)d_in[18];
    const float* Ws1c3 = (const float*)d_in[19];
    const float* Wp0  = (const float*)d_in[20];
    const float* Wp1  = (const float*)d_in[21];
    float* out = (float*)d_out;

    // C_SILU via trapezoid on R (matches Gauss-Hermite to <1e-7)
    double m2 = 0.0;
    const double hstep = 1.0 / 128.0;
    for (int i = -14 * 128; i <= 14 * 128; i++) {
        double z = i * hstep;
        double f = z / (1.0 + exp(-z));
        m2 += exp(-0.5 * z * z) * f * f;
    }
    m2 *= hstep / sqrt(2.0 * 3.141592653589793);
    float cs = (float)(1.0 / sqrt(m2));

    cudaFuncSetAttribute(mlp_kernel, cudaFuncAttributeMaxDynamicSharedMemorySize, 118784);
    cudaFuncSetAttribute(finalize_kernel, cudaFuncAttributeMaxDynamicSharedMemorySize, 176640);

    prep_kernel<<<108, 256>>>(Wm1, Wm2, Wm3, Wm4);      // wprep + zero deg/cursor
    hist_kernel<<<1250, 256>>>(je);
    scan_kernel<<<1, 1024>>>();
    scatter_kernel<<<1250, 256>>>(je, ie, ea);
    node_up_kernel<<<2500, 256>>>(nf, Wup0, Wup1);
    mlp_kernel<<<1250, 512, 118784>>>(ef, cs);
    msg_kernel<<<1250, 512>>>();
    finalize_kernel<<<296, 512, 176640>>>(Wl0, Wl1, Ws0c1, Ws0c2, Ws0c3,
                                          Ws1c1, Ws1c2, Ws1c3, Wp0, Wp1, zn, out);
}